// round 1
// baseline (speedup 1.0000x reference)
#include <cuda_runtime.h>
#include <mma.h>

using namespace nvcuda;

// Problem constants
#define BB 4
#define NN 2048
#define DD 1024
#define HH 16
#define DHH 64
#define MROWS (BB * NN)   // 8192

// ---------------- scratch (device globals; no runtime allocation) ----------
__device__ float g_xn[(size_t)MROWS * DD];          // layernormed x   [8192,1024]
__device__ float g_q [(size_t)BB * HH * NN * DHH];  // [b,h,n,dh]
__device__ float g_k [(size_t)BB * HH * NN * DHH];
__device__ float g_v [(size_t)BB * HH * NN * DHH];
__device__ float g_ao[(size_t)MROWS * DD];          // attention out   [8192,1024] (b,n,(h dh))

// ============================================================================
// LayerNorm: one block per row (8192 rows), 256 threads, 4 floats each.
// ============================================================================
__global__ void ln_kernel(const float* __restrict__ x, const float* __restrict__ g) {
    const int row = blockIdx.x;
    const int tid = threadIdx.x;
    const float4* xr = (const float4*)(x + (size_t)row * DD);
    float4 v = xr[tid];
    float s  = v.x + v.y + v.z + v.w;
    float ss = v.x*v.x + v.y*v.y + v.z*v.z + v.w*v.w;
    #pragma unroll
    for (int off = 16; off > 0; off >>= 1) {
        s  += __shfl_down_sync(0xffffffffu, s,  off);
        ss += __shfl_down_sync(0xffffffffu, ss, off);
    }
    __shared__ float s1[8], s2[8];
    __shared__ float mu_s, rstd_s;
    const int lane = tid & 31, wid = tid >> 5;
    if (lane == 0) { s1[wid] = s; s2[wid] = ss; }
    __syncthreads();
    if (tid == 0) {
        float t = 0.f, tt = 0.f;
        #pragma unroll
        for (int i = 0; i < 8; i++) { t += s1[i]; tt += s2[i]; }
        float mu  = t * (1.0f / DD);
        float var = tt * (1.0f / DD) - mu * mu;
        mu_s = mu;
        rstd_s = rsqrtf(var + 1e-5f);
    }
    __syncthreads();
    const float mu = mu_s, rstd = rstd_s;
    float4 gv = ((const float4*)g)[tid];
    float4 o;
    o.x = (v.x - mu) * rstd * gv.x;
    o.y = (v.y - mu) * rstd * gv.y;
    o.z = (v.z - mu) * rstd * gv.z;
    o.w = (v.w - mu) * rstd * gv.w;
    ((float4*)(g_xn + (size_t)row * DD))[tid] = o;
}

// ============================================================================
// TF32 wmma GEMM, 128x128x32 tiles, 8 warps (4x2), each warp 32x64.
// MODE 0: C = g_xn @ [Wq | Wkv]  -> scatter into g_q/g_k/g_v ([b,h,n,dh])
// MODE 1: C = g_ao @ Wo          -> dense output
// ============================================================================
template<int MODE>
__global__ void gemm_tf32(const float* __restrict__ Bq,
                          const float* __restrict__ Bkv,
                          float* __restrict__ C) {
    __shared__ float As[128 * 40];   // 128 x 32, stride 40
    __shared__ float Bs[32 * 136];   // 32 x 128, stride 136

    const float* A = (MODE == 0) ? g_xn : g_ao;

    const int m0 = blockIdx.y * 128;
    const int c0 = blockIdx.x * 128;

    const float* Bsrc;
    int ldb, bcol0;
    if (MODE == 1)      { Bsrc = Bq;  ldb = 1024; bcol0 = c0; }
    else if (c0 < 1024) { Bsrc = Bq;  ldb = 1024; bcol0 = c0; }
    else                { Bsrc = Bkv; ldb = 2048; bcol0 = c0 - 1024; }

    const int tid = threadIdx.x;
    const int wid = tid >> 5;
    const int warp_m = wid & 3;   // 0..3 -> 32 rows each
    const int warp_n = wid >> 2;  // 0..1 -> 64 cols each

    wmma::fragment<wmma::accumulator, 16, 16, 8, float> acc[2][4];
    #pragma unroll
    for (int i = 0; i < 2; i++)
        #pragma unroll
        for (int j = 0; j < 4; j++)
            wmma::fill_fragment(acc[i][j], 0.0f);

    const int arow = tid >> 3, ac4 = (tid & 7) * 4;
    const int brow = tid >> 5, bc4 = (tid & 31) * 4;

    for (int k0 = 0; k0 < DD; k0 += 32) {
        #pragma unroll
        for (int rr = 0; rr < 4; rr++) {
            int r = arow + rr * 32;
            *(float4*)&As[r * 40 + ac4] =
                *(const float4*)&A[(size_t)(m0 + r) * DD + k0 + ac4];
        }
        #pragma unroll
        for (int rr = 0; rr < 4; rr++) {
            int r = brow + rr * 8;
            *(float4*)&Bs[r * 136 + bc4] =
                *(const float4*)&Bsrc[(size_t)(k0 + r) * ldb + bcol0 + bc4];
        }
        __syncthreads();

        #pragma unroll
        for (int kk = 0; kk < 4; kk++) {
            wmma::fragment<wmma::matrix_a, 16, 16, 8, wmma::precision::tf32, wmma::row_major> af[2];
            #pragma unroll
            for (int i = 0; i < 2; i++) {
                wmma::load_matrix_sync(af[i], &As[(warp_m * 32 + i * 16) * 40 + kk * 8], 40);
                #pragma unroll
                for (int e = 0; e < af[i].num_elements; e++)
                    af[i].x[e] = wmma::__float_to_tf32(af[i].x[e]);
            }
            #pragma unroll
            for (int j = 0; j < 4; j++) {
                wmma::fragment<wmma::matrix_b, 16, 16, 8, wmma::precision::tf32, wmma::row_major> bf;
                wmma::load_matrix_sync(bf, &Bs[(kk * 8) * 136 + warp_n * 64 + j * 16], 136);
                #pragma unroll
                for (int e = 0; e < bf.num_elements; e++)
                    bf.x[e] = wmma::__float_to_tf32(bf.x[e]);
                #pragma unroll
                for (int i = 0; i < 2; i++)
                    wmma::mma_sync(acc[i][j], af[i], bf, acc[i][j]);
            }
        }
        __syncthreads();
    }

    // Epilogue
    #pragma unroll
    for (int i = 0; i < 2; i++) {
        #pragma unroll
        for (int j = 0; j < 4; j++) {
            const int row = m0 + warp_m * 32 + i * 16;
            const int col = c0 + warp_n * 64 + j * 16;
            if (MODE == 1) {
                wmma::store_matrix_sync(&C[(size_t)row * DD + col], acc[i][j], DD,
                                        wmma::mem_row_major);
            } else {
                float* dst; int cc;
                if (col < 1024)      { dst = g_q; cc = col; }
                else if (col < 2048) { dst = g_k; cc = col - 1024; }
                else                 { dst = g_v; cc = col - 2048; }
                const int b = row >> 11, n = row & 2047;
                const int h = cc >> 6,  dh = cc & 63;
                float* base = dst + (((size_t)(b * HH + h) * NN + n) * DHH + dh);
                wmma::store_matrix_sync(base, acc[i][j], DHH, wmma::mem_row_major);
            }
        }
    }
}

// ============================================================================
// Causal flash attention, fp32 softmax, TF32 wmma for QK^T and PV.
// Block = (64 q rows) x (one b,h). 128 threads / 4 warps.
// smem tiles stride 72; O kept in smem (wmma frag->row map is opaque).
// ============================================================================
#define TS (64 * 72)
#define ATTN_SMEM_BYTES ((6 * TS + 3 * 64) * 4)

__global__ void attn_kernel() {
    const int bh = blockIdx.y;       // b*H + h
    const int qt = blockIdx.x;       // q tile (64 rows)
    const int tid = threadIdx.x;     // 128
    const int wid = tid >> 5;

    extern __shared__ float sm[];
    float* Qs  = sm;
    float* Ks  = Qs  + TS;
    float* Vs  = Ks  + TS;
    float* Ss  = Vs  + TS;
    float* OPs = Ss  + TS;
    float* Os  = OPs + TS;
    float* m_s = Os  + TS;
    float* l_s = m_s + 64;
    float* al_s = l_s + 64;

    const size_t head_off = (size_t)bh * NN * DHH;
    const float* Qg = g_q + head_off + (size_t)qt * 64 * DHH;

    // Load Q tile 64x64
    for (int i = tid; i < 1024; i += 128) {
        const int r = i >> 4, c4 = (i & 15) * 4;
        *(float4*)&Qs[r * 72 + c4] = *(const float4*)&Qg[r * DHH + c4];
    }
    // Init O, m, l
    for (int i = tid; i < TS; i += 128) Os[i] = 0.0f;
    if (tid < 64) { m_s[tid] = -INFINITY; l_s[tid] = 0.0f; }
    __syncthreads();

    const float scale = 0.125f;  // 1/sqrt(64)

    for (int j = 0; j <= qt; j++) {
        // Load K, V tiles
        const float* Kg = g_k + head_off + (size_t)j * 64 * DHH;
        const float* Vg = g_v + head_off + (size_t)j * 64 * DHH;
        for (int i = tid; i < 1024; i += 128) {
            const int r = i >> 4, c4 = (i & 15) * 4;
            *(float4*)&Ks[r * 72 + c4] = *(const float4*)&Kg[r * DHH + c4];
            *(float4*)&Vs[r * 72 + c4] = *(const float4*)&Vg[r * DHH + c4];
        }
        __syncthreads();

        // S = Q @ K^T : each warp 16 rows x 64 cols
        {
            wmma::fragment<wmma::accumulator, 16, 16, 8, float> sacc[4];
            #pragma unroll
            for (int t = 0; t < 4; t++) wmma::fill_fragment(sacc[t], 0.0f);
            #pragma unroll
            for (int kk = 0; kk < 8; kk++) {
                wmma::fragment<wmma::matrix_a, 16, 16, 8, wmma::precision::tf32, wmma::row_major> af;
                wmma::load_matrix_sync(af, &Qs[(wid * 16) * 72 + kk * 8], 72);
                #pragma unroll
                for (int e = 0; e < af.num_elements; e++)
                    af.x[e] = wmma::__float_to_tf32(af.x[e]);
                #pragma unroll
                for (int t = 0; t < 4; t++) {
                    wmma::fragment<wmma::matrix_b, 16, 16, 8, wmma::precision::tf32, wmma::col_major> bf;
                    wmma::load_matrix_sync(bf, &Ks[(t * 16) * 72 + kk * 8], 72);
                    #pragma unroll
                    for (int e = 0; e < bf.num_elements; e++)
                        bf.x[e] = wmma::__float_to_tf32(bf.x[e]);
                    wmma::mma_sync(sacc[t], af, bf, sacc[t]);
                }
            }
            #pragma unroll
            for (int t = 0; t < 4; t++)
                wmma::store_matrix_sync(&Ss[(wid * 16) * 72 + t * 16], sacc[t], 72,
                                        wmma::mem_row_major);
        }
        __syncthreads();

        // Online softmax: 2 threads per row (32 cols each)
        {
            const int r = tid >> 1;
            const int halfc = (tid & 1) * 32;
            const int gi = qt * 64 + r;
            float* srow = &Ss[r * 72 + halfc];
            const bool diag = (j == qt);

            float mx = -INFINITY;
            #pragma unroll 8
            for (int c = 0; c < 32; c++) {
                float s = srow[c] * scale;
                if (diag && (j * 64 + halfc + c > gi)) s = -INFINITY;
                srow[c] = s;
                mx = fmaxf(mx, s);
            }
            mx = fmaxf(mx, __shfl_xor_sync(0xffffffffu, mx, 1));
            const float mold = m_s[r];
            const float mnew = fmaxf(mold, mx);
            float sum = 0.0f;
            #pragma unroll 8
            for (int c = 0; c < 32; c++) {
                float p = __expf(srow[c] - mnew);
                srow[c] = p;
                sum += p;
            }
            sum += __shfl_xor_sync(0xffffffffu, sum, 1);
            if ((tid & 1) == 0) {
                const float al = __expf(mold - mnew);
                al_s[r] = al;
                l_s[r] = l_s[r] * al + sum;
                m_s[r] = mnew;
            }
        }
        __syncthreads();

        // OP = P @ V
        {
            wmma::fragment<wmma::accumulator, 16, 16, 8, float> oacc[4];
            #pragma unroll
            for (int t = 0; t < 4; t++) wmma::fill_fragment(oacc[t], 0.0f);
            #pragma unroll
            for (int kk = 0; kk < 8; kk++) {
                wmma::fragment<wmma::matrix_a, 16, 16, 8, wmma::precision::tf32, wmma::row_major> af;
                wmma::load_matrix_sync(af, &Ss[(wid * 16) * 72 + kk * 8], 72);
                #pragma unroll
                for (int e = 0; e < af.num_elements; e++)
                    af.x[e] = wmma::__float_to_tf32(af.x[e]);
                #pragma unroll
                for (int t = 0; t < 4; t++) {
                    wmma::fragment<wmma::matrix_b, 16, 16, 8, wmma::precision::tf32, wmma::row_major> bf;
                    wmma::load_matrix_sync(bf, &Vs[(kk * 8) * 72 + t * 16], 72);
                    #pragma unroll
                    for (int e = 0; e < bf.num_elements; e++)
                        bf.x[e] = wmma::__float_to_tf32(bf.x[e]);
                    wmma::mma_sync(oacc[t], af, bf, oacc[t]);
                }
            }
            #pragma unroll
            for (int t = 0; t < 4; t++)
                wmma::store_matrix_sync(&OPs[(wid * 16) * 72 + t * 16], oacc[t], 72,
                                        wmma::mem_row_major);
        }
        __syncthreads();

        // O = O * alpha + OP
        for (int idx = tid; idx < 4096; idx += 128) {
            const int r = idx >> 6, c = idx & 63;
            Os[r * 72 + c] = Os[r * 72 + c] * al_s[r] + OPs[r * 72 + c];
        }
        __syncthreads();
    }

    // Write out: g_ao[(b*N + qi+r)*D + h*64 + c] = O[r][c] / l[r]
    {
        const int b = bh >> 4, h = bh & 15;
        float* Og = g_ao + ((size_t)(b * NN + qt * 64)) * DD + h * DHH;
        for (int idx = tid; idx < 4096; idx += 128) {
            const int r = idx >> 6, c = idx & 63;
            Og[(size_t)r * DD + c] = Os[r * 72 + c] / l_s[r];
        }
    }
}

// ============================================================================
// Launch
// ============================================================================
extern "C" void kernel_launch(void* const* d_in, const int* in_sizes, int n_in,
                              void* d_out, int out_size) {
    (void)in_sizes; (void)n_in; (void)out_size;
    const float* x   = (const float*)d_in[0];
    const float* g   = (const float*)d_in[1];
    const float* Wq  = (const float*)d_in[2];
    const float* Wkv = (const float*)d_in[3];
    const float* Wo  = (const float*)d_in[4];
    float* out = (float*)d_out;

    // 1) LayerNorm
    ln_kernel<<<MROWS, 256>>>(x, g);

    // 2) Fused QKV projection (M=8192, N=3072)
    gemm_tf32<0><<<dim3(24, 64), 256>>>(Wq, Wkv, nullptr);

    // 3) Causal flash attention
    cudaFuncSetAttribute(attn_kernel, cudaFuncAttributeMaxDynamicSharedMemorySize,
                         ATTN_SMEM_BYTES);
    attn_kernel<<<dim3(32, BB * HH), 128, ATTN_SMEM_BYTES>>>();

    // 4) Output projection (M=8192, N=1024)
    gemm_tf32<1><<<dim3(8, 64), 256>>>(Wo, nullptr, out);
}

// round 2
// speedup vs baseline: 1.6200x; 1.6200x over previous
#include <cuda_runtime.h>
#include <mma.h>
#include <cstdint>

using namespace nvcuda;

#define BB 4
#define NN 2048
#define DD 1024
#define HH 16
#define DHH 64
#define MROWS (BB * NN)   // 8192

// ---------------- scratch (device globals; no runtime allocation) ----------
__device__ float g_xn[(size_t)MROWS * DD];
__device__ float g_q [(size_t)MROWS * DD];   // [b,h,n,dh]
__device__ float g_k [(size_t)MROWS * DD];
__device__ float g_v [(size_t)MROWS * DD];
__device__ float g_ao[(size_t)MROWS * DD];   // [b,n,(h dh)]

// ---------------- small PTX helpers ----------------------------------------
__device__ __forceinline__ uint32_t f2tf32(float f) {
    uint32_t u;
    asm("cvt.rna.tf32.f32 %0, %1;" : "=r"(u) : "f"(f));
    return u;
}
__device__ __forceinline__ void mma_tf32(float* d, const uint32_t* a,
                                         uint32_t b0, uint32_t b1) {
    asm volatile(
        "mma.sync.aligned.m16n8k8.row.col.f32.tf32.tf32.f32 "
        "{%0,%1,%2,%3},{%4,%5,%6,%7},{%8,%9},{%0,%1,%2,%3};\n"
        : "+f"(d[0]), "+f"(d[1]), "+f"(d[2]), "+f"(d[3])
        : "r"(a[0]), "r"(a[1]), "r"(a[2]), "r"(a[3]), "r"(b0), "r"(b1));
}
__device__ __forceinline__ void cp16(uint32_t dst, const void* src) {
    asm volatile("cp.async.cg.shared.global [%0], [%1], 16;\n"
                 :: "r"(dst), "l"(src));
}
__device__ __forceinline__ void cp_commit() {
    asm volatile("cp.async.commit_group;\n" ::);
}

// ============================================================================
// LayerNorm: one block per row, 256 threads, 4 floats each.
// ============================================================================
__global__ void ln_kernel(const float* __restrict__ x, const float* __restrict__ g) {
    const int row = blockIdx.x;
    const int tid = threadIdx.x;
    const float4* xr = (const float4*)(x + (size_t)row * DD);
    float4 v = xr[tid];
    float s  = v.x + v.y + v.z + v.w;
    float ss = v.x*v.x + v.y*v.y + v.z*v.z + v.w*v.w;
    #pragma unroll
    for (int off = 16; off > 0; off >>= 1) {
        s  += __shfl_down_sync(0xffffffffu, s,  off);
        ss += __shfl_down_sync(0xffffffffu, ss, off);
    }
    __shared__ float s1[8], s2[8];
    __shared__ float mu_s, rstd_s;
    const int lane = tid & 31, wid = tid >> 5;
    if (lane == 0) { s1[wid] = s; s2[wid] = ss; }
    __syncthreads();
    if (tid == 0) {
        float t = 0.f, tt = 0.f;
        #pragma unroll
        for (int i = 0; i < 8; i++) { t += s1[i]; tt += s2[i]; }
        float mu  = t * (1.0f / DD);
        float var = tt * (1.0f / DD) - mu * mu;
        mu_s = mu;
        rstd_s = rsqrtf(var + 1e-5f);
    }
    __syncthreads();
    const float mu = mu_s, rstd = rstd_s;
    float4 gv = ((const float4*)g)[tid];
    float4 o;
    o.x = (v.x - mu) * rstd * gv.x;
    o.y = (v.y - mu) * rstd * gv.y;
    o.z = (v.z - mu) * rstd * gv.z;
    o.w = (v.w - mu) * rstd * gv.w;
    ((float4*)(g_xn + (size_t)row * DD))[tid] = o;
}

// ============================================================================
// TF32 wmma GEMM, 128x128x32 tiles, double-buffered cp.async pipeline.
// MODE 0: C = g_xn @ [Wq | Wkv]  -> scatter into g_q/g_k/g_v ([b,h,n,dh])
// MODE 1: C = g_ao @ Wo          -> dense output
// ============================================================================
#define GEMM_AS (128 * 40)
#define GEMM_BS (32 * 136)
#define GEMM_SMEM_BYTES ((2 * GEMM_AS + 2 * GEMM_BS) * 4)

template<int MODE>
__global__ void gemm_tf32(const float* __restrict__ Bq,
                          const float* __restrict__ Bkv,
                          float* __restrict__ C) {
    extern __shared__ float sm[];
    float* Asm[2] = { sm, sm + GEMM_AS };
    float* Bsm[2] = { sm + 2 * GEMM_AS, sm + 2 * GEMM_AS + GEMM_BS };
    const uint32_t sbase = (uint32_t)__cvta_generic_to_shared(sm);

    const float* A = (MODE == 0) ? g_xn : g_ao;

    const int m0 = blockIdx.y * 128;
    const int c0 = blockIdx.x * 128;

    const float* Bsrc;
    int ldb, bcol0;
    if (MODE == 1)      { Bsrc = Bq;  ldb = 1024; bcol0 = c0; }
    else if (c0 < 1024) { Bsrc = Bq;  ldb = 1024; bcol0 = c0; }
    else                { Bsrc = Bkv; ldb = 2048; bcol0 = c0 - 1024; }

    const int tid = threadIdx.x;
    const int wid = tid >> 5;
    const int warp_m = wid & 3;
    const int warp_n = wid >> 2;

    wmma::fragment<wmma::accumulator, 16, 16, 8, float> acc[2][4];
    #pragma unroll
    for (int i = 0; i < 2; i++)
        #pragma unroll
        for (int j = 0; j < 4; j++)
            wmma::fill_fragment(acc[i][j], 0.0f);

    const int arow = tid >> 3, ac4 = (tid & 7) * 4;
    const int brow = tid >> 5, bc4 = (tid & 31) * 4;

    auto load_tile = [&](int k0, int buf) {
        const uint32_t abase = sbase + (uint32_t)(buf * GEMM_AS) * 4;
        const uint32_t bbase = sbase + (uint32_t)(2 * GEMM_AS + buf * GEMM_BS) * 4;
        #pragma unroll
        for (int rr = 0; rr < 4; rr++) {
            const int r = arow + rr * 32;
            cp16(abase + (uint32_t)(r * 40 + ac4) * 4,
                 &A[(size_t)(m0 + r) * DD + k0 + ac4]);
        }
        #pragma unroll
        for (int rr = 0; rr < 4; rr++) {
            const int r = brow + rr * 8;
            cp16(bbase + (uint32_t)(r * 136 + bc4) * 4,
                 &Bsrc[(size_t)(k0 + r) * ldb + bcol0 + bc4]);
        }
        cp_commit();
    };

    load_tile(0, 0);
    int buf = 0;
    for (int k0 = 0; k0 < DD; k0 += 32) {
        if (k0 + 32 < DD) {
            load_tile(k0 + 32, buf ^ 1);
            asm volatile("cp.async.wait_group 1;\n" ::);
        } else {
            asm volatile("cp.async.wait_group 0;\n" ::);
        }
        __syncthreads();

        float* As = Asm[buf];
        float* Bs = Bsm[buf];
        #pragma unroll
        for (int kk = 0; kk < 4; kk++) {
            wmma::fragment<wmma::matrix_a, 16, 16, 8, wmma::precision::tf32, wmma::row_major> af[2];
            #pragma unroll
            for (int i = 0; i < 2; i++) {
                wmma::load_matrix_sync(af[i], &As[(warp_m * 32 + i * 16) * 40 + kk * 8], 40);
                #pragma unroll
                for (int e = 0; e < af[i].num_elements; e++)
                    af[i].x[e] = wmma::__float_to_tf32(af[i].x[e]);
            }
            #pragma unroll
            for (int j = 0; j < 4; j++) {
                wmma::fragment<wmma::matrix_b, 16, 16, 8, wmma::precision::tf32, wmma::row_major> bf;
                wmma::load_matrix_sync(bf, &Bs[(kk * 8) * 136 + warp_n * 64 + j * 16], 136);
                #pragma unroll
                for (int e = 0; e < bf.num_elements; e++)
                    bf.x[e] = wmma::__float_to_tf32(bf.x[e]);
                #pragma unroll
                for (int i = 0; i < 2; i++)
                    wmma::mma_sync(acc[i][j], af[i], bf, acc[i][j]);
            }
        }
        __syncthreads();
        buf ^= 1;
    }

    // Epilogue
    #pragma unroll
    for (int i = 0; i < 2; i++) {
        #pragma unroll
        for (int j = 0; j < 4; j++) {
            const int row = m0 + warp_m * 32 + i * 16;
            const int col = c0 + warp_n * 64 + j * 16;
            if (MODE == 1) {
                wmma::store_matrix_sync(&C[(size_t)row * DD + col], acc[i][j], DD,
                                        wmma::mem_row_major);
            } else {
                float* dst; int cc;
                if (col < 1024)      { dst = g_q; cc = col; }
                else if (col < 2048) { dst = g_k; cc = col - 1024; }
                else                 { dst = g_v; cc = col - 2048; }
                const int b = row >> 11, n = row & 2047;
                const int h = cc >> 6,  dh = cc & 63;
                float* base = dst + (((size_t)(b * HH + h) * NN + n) * DHH + dh);
                wmma::store_matrix_sync(base, acc[i][j], DHH, wmma::mem_row_major);
            }
        }
    }
}

// ============================================================================
// Causal flash attention. PTX mma m16n8k8 tf32, O in registers.
// Block = 128 q rows x (one b,h). 256 threads / 8 warps, warp owns 16 rows.
// K/V double-buffered via cp.async. P round-trips through warp-private smem.
// ============================================================================
#define KST 68
#define VST 72
#define PST 68
#define ATTN_SMEM_BYTES ((2*64*KST + 2*64*VST + 128*PST) * 4)

__global__ __launch_bounds__(256) void attn_kernel() {
    extern __shared__ float sm[];
    float* Ks = sm;                         // [2][64][KST]
    float* Vs = sm + 2 * 64 * KST;          // [2][64][VST]
    float* Ps = sm + 2 * 64 * KST + 2 * 64 * VST;  // [128][PST]
    const uint32_t sbase = (uint32_t)__cvta_generic_to_shared(sm);
    const uint32_t ks_u = sbase;
    const uint32_t vs_u = sbase + (uint32_t)(2 * 64 * KST) * 4;

    const int qt = blockIdx.x;    // q tile of 128 rows (0..15)
    const int bh = blockIdx.y;    // b*H + h (0..63)
    const int tid = threadIdx.x;
    const int w = tid >> 5;
    const int lane = tid & 31;
    const int g = lane >> 2;      // group id 0..7
    const int c = lane & 3;       // tid in group

    const size_t hoff = (size_t)bh * NN * DHH;
    const float* Qg  = g_q + hoff + (size_t)qt * 128 * DHH;
    const float* Kg0 = g_k + hoff;
    const float* Vg0 = g_v + hoff;

    // Q fragments (held in regs for whole block), pre-scaled by 1/sqrt(dh)
    uint32_t aQ[8][4];
    {
        const int r0 = w * 16 + g, r1 = r0 + 8;
        #pragma unroll
        for (int kk = 0; kk < 8; kk++) {
            aQ[kk][0] = f2tf32(Qg[r0 * DHH + kk * 8 + c]     * 0.125f);
            aQ[kk][1] = f2tf32(Qg[r1 * DHH + kk * 8 + c]     * 0.125f);
            aQ[kk][2] = f2tf32(Qg[r0 * DHH + kk * 8 + c + 4] * 0.125f);
            aQ[kk][3] = f2tf32(Qg[r1 * DHH + kk * 8 + c + 4] * 0.125f);
        }
    }

    float o[8][4];
    #pragma unroll
    for (int t = 0; t < 8; t++)
        #pragma unroll
        for (int e = 0; e < 4; e++) o[t][e] = 0.0f;
    float m0v = -INFINITY, m1v = -INFINITY, l0 = 0.0f, l1 = 0.0f;

    const int jmax = 2 * qt + 1;
    const int lr  = tid >> 4;          // load row base (0..15)
    const int lc4 = (tid & 15) * 4;    // load col

    auto prefetch = [&](int j, int buf) {
        const float* Kg = Kg0 + (size_t)j * 64 * DHH;
        const float* Vg = Vg0 + (size_t)j * 64 * DHH;
        #pragma unroll
        for (int rr = 0; rr < 4; rr++) {
            const int r = lr + rr * 16;
            cp16(ks_u + (uint32_t)((buf * 64 + r) * KST + lc4) * 4, &Kg[r * DHH + lc4]);
            cp16(vs_u + (uint32_t)((buf * 64 + r) * VST + lc4) * 4, &Vg[r * DHH + lc4]);
        }
        cp_commit();
    };

    prefetch(0, 0);
    const int row0g = qt * 128 + w * 16;   // warp's first global q row

    for (int j = 0; j <= jmax; j++) {
        if (j < jmax) {
            prefetch(j + 1, (j + 1) & 1);
            asm volatile("cp.async.wait_group 1;\n" ::);
        } else {
            asm volatile("cp.async.wait_group 0;\n" ::);
        }
        __syncthreads();

        const bool skip = (j * 64 > row0g + 15);   // tile fully masked for warp
        if (!skip) {
            float* Kb = Ks + (j & 1) * 64 * KST;
            float* Vb = Vs + (j & 1) * 64 * VST;

            // ---- S = (Q*scale) @ K^T : 16 x 64 per warp
            float s[8][4];
            #pragma unroll
            for (int t = 0; t < 8; t++)
                #pragma unroll
                for (int e = 0; e < 4; e++) s[t][e] = 0.0f;

            #pragma unroll
            for (int kk = 0; kk < 8; kk++) {
                #pragma unroll
                for (int t = 0; t < 8; t++) {
                    const uint32_t b0 = f2tf32(Kb[(t * 8 + g) * KST + kk * 8 + c]);
                    const uint32_t b1 = f2tf32(Kb[(t * 8 + g) * KST + kk * 8 + c + 4]);
                    mma_tf32(s[t], aQ[kk], b0, b1);
                }
            }

            // ---- causal mask (only near diagonal)
            if (j * 64 + 63 > row0g) {
                const int r0 = row0g + g, r1 = r0 + 8;
                #pragma unroll
                for (int t = 0; t < 8; t++) {
                    const int col = j * 64 + t * 8 + 2 * c;
                    if (col     > r0) s[t][0] = -INFINITY;
                    if (col + 1 > r0) s[t][1] = -INFINITY;
                    if (col     > r1) s[t][2] = -INFINITY;
                    if (col + 1 > r1) s[t][3] = -INFINITY;
                }
            }

            // ---- online softmax in registers (2 rows per thread)
            float mx0 = -INFINITY, mx1 = -INFINITY;
            #pragma unroll
            for (int t = 0; t < 8; t++) {
                mx0 = fmaxf(mx0, fmaxf(s[t][0], s[t][1]));
                mx1 = fmaxf(mx1, fmaxf(s[t][2], s[t][3]));
            }
            mx0 = fmaxf(mx0, __shfl_xor_sync(0xffffffffu, mx0, 1));
            mx0 = fmaxf(mx0, __shfl_xor_sync(0xffffffffu, mx0, 2));
            mx1 = fmaxf(mx1, __shfl_xor_sync(0xffffffffu, mx1, 1));
            mx1 = fmaxf(mx1, __shfl_xor_sync(0xffffffffu, mx1, 2));

            const float mn0 = fmaxf(m0v, mx0);
            const float mn1 = fmaxf(m1v, mx1);
            float sum0 = 0.0f, sum1 = 0.0f;
            #pragma unroll
            for (int t = 0; t < 8; t++) {
                s[t][0] = __expf(s[t][0] - mn0);
                s[t][1] = __expf(s[t][1] - mn0);
                s[t][2] = __expf(s[t][2] - mn1);
                s[t][3] = __expf(s[t][3] - mn1);
                sum0 += s[t][0] + s[t][1];
                sum1 += s[t][2] + s[t][3];
            }
            sum0 += __shfl_xor_sync(0xffffffffu, sum0, 1);
            sum0 += __shfl_xor_sync(0xffffffffu, sum0, 2);
            sum1 += __shfl_xor_sync(0xffffffffu, sum1, 1);
            sum1 += __shfl_xor_sync(0xffffffffu, sum1, 2);

            const float al0 = __expf(m0v - mn0);
            const float al1 = __expf(m1v - mn1);
            l0 = l0 * al0 + sum0;
            l1 = l1 * al1 + sum1;
            m0v = mn0; m1v = mn1;

            // rescale O accumulators in registers
            #pragma unroll
            for (int t = 0; t < 8; t++) {
                o[t][0] *= al0; o[t][1] *= al0;
                o[t][2] *= al1; o[t][3] *= al1;
            }

            // ---- P to warp-private smem (C-layout -> A-layout remap)
            float* Pw = Ps + (w * 16) * PST;
            __syncwarp();
            #pragma unroll
            for (int t = 0; t < 8; t++) {
                *(float2*)&Pw[ g      * PST + t * 8 + 2 * c] = make_float2(s[t][0], s[t][1]);
                *(float2*)&Pw[(g + 8) * PST + t * 8 + 2 * c] = make_float2(s[t][2], s[t][3]);
            }
            __syncwarp();

            // ---- O += P @ V
            #pragma unroll
            for (int kk = 0; kk < 8; kk++) {
                uint32_t a[4];
                a[0] = f2tf32(Pw[ g      * PST + kk * 8 + c]);
                a[1] = f2tf32(Pw[(g + 8) * PST + kk * 8 + c]);
                a[2] = f2tf32(Pw[ g      * PST + kk * 8 + c + 4]);
                a[3] = f2tf32(Pw[(g + 8) * PST + kk * 8 + c + 4]);
                #pragma unroll
                for (int t = 0; t < 8; t++) {
                    const uint32_t b0 = f2tf32(Vb[(kk * 8 + c)     * VST + t * 8 + g]);
                    const uint32_t b1 = f2tf32(Vb[(kk * 8 + c + 4) * VST + t * 8 + g]);
                    mma_tf32(o[t], a, b0, b1);
                }
            }
        }
        __syncthreads();
    }

    // ---- write out: g_ao[(b*N + row)*D + h*64 + col] = O / l
    const int b = bh >> 4, h = bh & 15;
    float* Og = g_ao + ((size_t)(b * NN + qt * 128)) * DD + h * DHH;
    const float i0 = 1.0f / l0, i1 = 1.0f / l1;
    const int r0 = w * 16 + g, r1 = r0 + 8;
    #pragma unroll
    for (int t = 0; t < 8; t++) {
        *(float2*)&Og[(size_t)r0 * DD + t * 8 + 2 * c] =
            make_float2(o[t][0] * i0, o[t][1] * i0);
        *(float2*)&Og[(size_t)r1 * DD + t * 8 + 2 * c] =
            make_float2(o[t][2] * i1, o[t][3] * i1);
    }
}

// ============================================================================
// Launch
// ============================================================================
extern "C" void kernel_launch(void* const* d_in, const int* in_sizes, int n_in,
                              void* d_out, int out_size) {
    (void)in_sizes; (void)n_in; (void)out_size;
    const float* x   = (const float*)d_in[0];
    const float* g   = (const float*)d_in[1];
    const float* Wq  = (const float*)d_in[2];
    const float* Wkv = (const float*)d_in[3];
    const float* Wo  = (const float*)d_in[4];
    float* out = (float*)d_out;

    cudaFuncSetAttribute(gemm_tf32<0>, cudaFuncAttributeMaxDynamicSharedMemorySize,
                         GEMM_SMEM_BYTES);
    cudaFuncSetAttribute(gemm_tf32<1>, cudaFuncAttributeMaxDynamicSharedMemorySize,
                         GEMM_SMEM_BYTES);
    cudaFuncSetAttribute(attn_kernel, cudaFuncAttributeMaxDynamicSharedMemorySize,
                         ATTN_SMEM_BYTES);

    // 1) LayerNorm
    ln_kernel<<<MROWS, 256>>>(x, g);

    // 2) Fused QKV projection (M=8192, N=3072)
    gemm_tf32<0><<<dim3(24, 64), 256, GEMM_SMEM_BYTES>>>(Wq, Wkv, nullptr);

    // 3) Causal flash attention (128-row q tiles)
    attn_kernel<<<dim3(16, BB * HH), 256, ATTN_SMEM_BYTES>>>();

    // 4) Output projection (M=8192, N=1024)
    gemm_tf32<1><<<dim3(8, 64), 256, GEMM_SMEM_BYTES>>>(Wo, nullptr, out);
}

// round 3
// speedup vs baseline: 1.7309x; 1.0685x over previous
#include <cuda_runtime.h>
#include <mma.h>
#include <cstdint>

using namespace nvcuda;

#define BB 4
#define NN 2048
#define DD 1024
#define HH 16
#define DHH 64
#define MROWS (BB * NN)   // 8192

// ---------------- scratch (device globals; no runtime allocation) ----------
__device__ float g_xn[(size_t)MROWS * DD];   // tf32-rounded LN output
__device__ float g_q [(size_t)MROWS * DD];   // [b,h,n,dh], tf32-rounded
__device__ float g_k [(size_t)MROWS * DD];
__device__ float g_v [(size_t)MROWS * DD];
__device__ float g_ao[(size_t)MROWS * DD];   // [b,n,(h dh)], tf32-rounded
__device__ float g_wq [(size_t)DD * DD];     // tf32-rounded weights
__device__ float g_wkv[(size_t)DD * 2 * DD];
__device__ float g_wo [(size_t)DD * DD];

// ---------------- small PTX helpers ----------------------------------------
__device__ __forceinline__ uint32_t f2tf32(float f) {
    uint32_t u;
    asm("cvt.rna.tf32.f32 %0, %1;" : "=r"(u) : "f"(f));
    return u;
}
__device__ __forceinline__ float roundtf(float f) {
    return __uint_as_float(f2tf32(f));
}
__device__ __forceinline__ void mma_tf32(float* d, const uint32_t* a,
                                         uint32_t b0, uint32_t b1) {
    asm volatile(
        "mma.sync.aligned.m16n8k8.row.col.f32.tf32.tf32.f32 "
        "{%0,%1,%2,%3},{%4,%5,%6,%7},{%8,%9},{%0,%1,%2,%3};\n"
        : "+f"(d[0]), "+f"(d[1]), "+f"(d[2]), "+f"(d[3])
        : "r"(a[0]), "r"(a[1]), "r"(a[2]), "r"(a[3]), "r"(b0), "r"(b1));
}
__device__ __forceinline__ void cp16(uint32_t dst, const void* src) {
    asm volatile("cp.async.cg.shared.global [%0], [%1], 16;\n"
                 :: "r"(dst), "l"(src));
}
__device__ __forceinline__ void cp_commit() {
    asm volatile("cp.async.commit_group;\n" ::);
}

// ============================================================================
// Round weights to tf32 once per launch. 1M float4s total.
// ============================================================================
__global__ void round_weights(const float* __restrict__ wq,
                              const float* __restrict__ wkv,
                              const float* __restrict__ wo) {
    const int i = blockIdx.x * blockDim.x + threadIdx.x;  // float4 index
    const float4* src; float4* dst; int off;
    if (i < 262144)      { src = (const float4*)wq;  dst = (float4*)g_wq;  off = i; }
    else if (i < 786432) { src = (const float4*)wkv; dst = (float4*)g_wkv; off = i - 262144; }
    else                 { src = (const float4*)wo;  dst = (float4*)g_wo;  off = i - 786432; }
    float4 v = src[off];
    v.x = roundtf(v.x); v.y = roundtf(v.y); v.z = roundtf(v.z); v.w = roundtf(v.w);
    dst[off] = v;
}

// ============================================================================
// LayerNorm: one block per row, 256 threads, 4 floats each. tf32-rounded out.
// ============================================================================
__global__ void ln_kernel(const float* __restrict__ x, const float* __restrict__ g) {
    const int row = blockIdx.x;
    const int tid = threadIdx.x;
    const float4* xr = (const float4*)(x + (size_t)row * DD);
    float4 v = xr[tid];
    float s  = v.x + v.y + v.z + v.w;
    float ss = v.x*v.x + v.y*v.y + v.z*v.z + v.w*v.w;
    #pragma unroll
    for (int off = 16; off > 0; off >>= 1) {
        s  += __shfl_down_sync(0xffffffffu, s,  off);
        ss += __shfl_down_sync(0xffffffffu, ss, off);
    }
    __shared__ float s1[8], s2[8];
    __shared__ float mu_s, rstd_s;
    const int lane = tid & 31, wid = tid >> 5;
    if (lane == 0) { s1[wid] = s; s2[wid] = ss; }
    __syncthreads();
    if (tid == 0) {
        float t = 0.f, tt = 0.f;
        #pragma unroll
        for (int i = 0; i < 8; i++) { t += s1[i]; tt += s2[i]; }
        float mu  = t * (1.0f / DD);
        float var = tt * (1.0f / DD) - mu * mu;
        mu_s = mu;
        rstd_s = rsqrtf(var + 1e-5f);
    }
    __syncthreads();
    const float mu = mu_s, rstd = rstd_s;
    float4 gv = ((const float4*)g)[tid];
    float4 o;
    o.x = roundtf((v.x - mu) * rstd * gv.x);
    o.y = roundtf((v.y - mu) * rstd * gv.y);
    o.z = roundtf((v.z - mu) * rstd * gv.z);
    o.w = roundtf((v.w - mu) * rstd * gv.w);
    ((float4*)(g_xn + (size_t)row * DD))[tid] = o;
}

// ============================================================================
// TF32 wmma GEMM, 128x128x32 tiles, double-buffered cp.async.
// All operands pre-rounded to tf32 -> NO cvt in the hot loop.
// MODE 0: C = g_xn @ [g_wq | g_wkv] -> scatter (tf32-rounded) into g_q/g_k/g_v
// MODE 1: C = g_ao @ g_wo           -> dense fp32 output
// ============================================================================
#define GEMM_AS (128 * 40)
#define GEMM_BS (32 * 132)
#define GEMM_SMEM_BYTES ((2 * GEMM_AS + 2 * GEMM_BS) * 4)

template<int MODE>
__global__ __launch_bounds__(256, 2) void gemm_tf32(float* __restrict__ C) {
    extern __shared__ float sm[];
    float* Asm[2] = { sm, sm + GEMM_AS };
    float* Bsm[2] = { sm + 2 * GEMM_AS, sm + 2 * GEMM_AS + GEMM_BS };
    const uint32_t sbase = (uint32_t)__cvta_generic_to_shared(sm);

    const float* A = (MODE == 0) ? g_xn : g_ao;

    const int m0 = blockIdx.y * 128;
    const int c0 = blockIdx.x * 128;

    const float* Bsrc;
    int ldb, bcol0;
    if (MODE == 1)      { Bsrc = g_wo;  ldb = 1024; bcol0 = c0; }
    else if (c0 < 1024) { Bsrc = g_wq;  ldb = 1024; bcol0 = c0; }
    else                { Bsrc = g_wkv; ldb = 2048; bcol0 = c0 - 1024; }

    const int tid = threadIdx.x;
    const int wid = tid >> 5;
    const int warp_m = wid & 3;
    const int warp_n = wid >> 2;

    wmma::fragment<wmma::accumulator, 16, 16, 8, float> acc[2][4];
    #pragma unroll
    for (int i = 0; i < 2; i++)
        #pragma unroll
        for (int j = 0; j < 4; j++)
            wmma::fill_fragment(acc[i][j], 0.0f);

    const int arow = tid >> 3, ac4 = (tid & 7) * 4;
    const int brow = tid >> 5, bc4 = (tid & 31) * 4;

    auto load_tile = [&](int k0, int buf) {
        const uint32_t abase = sbase + (uint32_t)(buf * GEMM_AS) * 4;
        const uint32_t bbase = sbase + (uint32_t)(2 * GEMM_AS + buf * GEMM_BS) * 4;
        #pragma unroll
        for (int rr = 0; rr < 4; rr++) {
            const int r = arow + rr * 32;
            cp16(abase + (uint32_t)(r * 40 + ac4) * 4,
                 &A[(size_t)(m0 + r) * DD + k0 + ac4]);
        }
        #pragma unroll
        for (int rr = 0; rr < 4; rr++) {
            const int r = brow + rr * 8;
            cp16(bbase + (uint32_t)(r * 132 + bc4) * 4,
                 &Bsrc[(size_t)(k0 + r) * ldb + bcol0 + bc4]);
        }
        cp_commit();
    };

    load_tile(0, 0);
    int buf = 0;
    for (int k0 = 0; k0 < DD; k0 += 32) {
        if (k0 + 32 < DD) {
            load_tile(k0 + 32, buf ^ 1);
            asm volatile("cp.async.wait_group 1;\n" ::);
        } else {
            asm volatile("cp.async.wait_group 0;\n" ::);
        }
        __syncthreads();

        float* As = Asm[buf];
        float* Bs = Bsm[buf];
        #pragma unroll
        for (int kk = 0; kk < 4; kk++) {
            wmma::fragment<wmma::matrix_a, 16, 16, 8, wmma::precision::tf32, wmma::row_major> af[2];
            #pragma unroll
            for (int i = 0; i < 2; i++)
                wmma::load_matrix_sync(af[i], &As[(warp_m * 32 + i * 16) * 40 + kk * 8], 40);
            #pragma unroll
            for (int j = 0; j < 4; j++) {
                wmma::fragment<wmma::matrix_b, 16, 16, 8, wmma::precision::tf32, wmma::row_major> bf;
                wmma::load_matrix_sync(bf, &Bs[(kk * 8) * 132 + warp_n * 64 + j * 16], 132);
                #pragma unroll
                for (int i = 0; i < 2; i++)
                    wmma::mma_sync(acc[i][j], af[i], bf, acc[i][j]);
            }
        }
        __syncthreads();
        buf ^= 1;
    }

    // Epilogue
    #pragma unroll
    for (int i = 0; i < 2; i++) {
        #pragma unroll
        for (int j = 0; j < 4; j++) {
            const int row = m0 + warp_m * 32 + i * 16;
            const int col = c0 + warp_n * 64 + j * 16;
            if (MODE == 1) {
                wmma::store_matrix_sync(&C[(size_t)row * DD + col], acc[i][j], DD,
                                        wmma::mem_row_major);
            } else {
                // round to tf32 so the attention kernel consumes raw bits
                #pragma unroll
                for (int e = 0; e < acc[i][j].num_elements; e++)
                    acc[i][j].x[e] = roundtf(acc[i][j].x[e]);
                float* dst; int cc;
                if (col < 1024)      { dst = g_q; cc = col; }
                else if (col < 2048) { dst = g_k; cc = col - 1024; }
                else                 { dst = g_v; cc = col - 2048; }
                const int b = row >> 11, n = row & 2047;
                const int h = cc >> 6,  dh = cc & 63;
                float* base = dst + (((size_t)(b * HH + h) * NN + n) * DHH + dh);
                wmma::store_matrix_sync(base, acc[i][j], DHH, wmma::mem_row_major);
            }
        }
    }
}

// ============================================================================
// Causal flash attention. PTX mma m16n8k8 tf32, O in registers.
// Q/K/V pre-rounded tf32 -> raw bit feed (no cvt). P cvt'd post-exp only.
// ============================================================================
#define KST 68
#define VST 72
#define PST 68
#define ATTN_SMEM_BYTES ((2*64*KST + 2*64*VST + 128*PST) * 4)

__global__ __launch_bounds__(256) void attn_kernel() {
    extern __shared__ float sm[];
    float* Ks = sm;                                  // [2][64][KST]
    float* Vs = sm + 2 * 64 * KST;                   // [2][64][VST]
    float* Ps = sm + 2 * 64 * KST + 2 * 64 * VST;    // [128][PST]
    const uint32_t sbase = (uint32_t)__cvta_generic_to_shared(sm);
    const uint32_t ks_u = sbase;
    const uint32_t vs_u = sbase + (uint32_t)(2 * 64 * KST) * 4;

    const int qt = blockIdx.x;
    const int bh = blockIdx.y;
    const int tid = threadIdx.x;
    const int w = tid >> 5;
    const int lane = tid & 31;
    const int g = lane >> 2;
    const int c = lane & 3;

    const size_t hoff = (size_t)bh * NN * DHH;
    const float* Qg  = g_q + hoff + (size_t)qt * 128 * DHH;
    const float* Kg0 = g_k + hoff;
    const float* Vg0 = g_v + hoff;

    // Q fragments: pre-rounded; *0.125 is an exact exponent shift.
    uint32_t aQ[8][4];
    {
        const int r0 = w * 16 + g, r1 = r0 + 8;
        #pragma unroll
        for (int kk = 0; kk < 8; kk++) {
            aQ[kk][0] = __float_as_uint(Qg[r0 * DHH + kk * 8 + c]     * 0.125f);
            aQ[kk][1] = __float_as_uint(Qg[r1 * DHH + kk * 8 + c]     * 0.125f);
            aQ[kk][2] = __float_as_uint(Qg[r0 * DHH + kk * 8 + c + 4] * 0.125f);
            aQ[kk][3] = __float_as_uint(Qg[r1 * DHH + kk * 8 + c + 4] * 0.125f);
        }
    }

    float o[8][4];
    #pragma unroll
    for (int t = 0; t < 8; t++)
        #pragma unroll
        for (int e = 0; e < 4; e++) o[t][e] = 0.0f;
    float m0v = -INFINITY, m1v = -INFINITY, l0 = 0.0f, l1 = 0.0f;

    const int jmax = 2 * qt + 1;
    const int lr  = tid >> 4;
    const int lc4 = (tid & 15) * 4;

    auto prefetch = [&](int j, int buf) {
        const float* Kg = Kg0 + (size_t)j * 64 * DHH;
        const float* Vg = Vg0 + (size_t)j * 64 * DHH;
        #pragma unroll
        for (int rr = 0; rr < 4; rr++) {
            const int r = lr + rr * 16;
            cp16(ks_u + (uint32_t)((buf * 64 + r) * KST + lc4) * 4, &Kg[r * DHH + lc4]);
            cp16(vs_u + (uint32_t)((buf * 64 + r) * VST + lc4) * 4, &Vg[r * DHH + lc4]);
        }
        cp_commit();
    };

    prefetch(0, 0);
    const int row0g = qt * 128 + w * 16;

    for (int j = 0; j <= jmax; j++) {
        if (j < jmax) {
            prefetch(j + 1, (j + 1) & 1);
            asm volatile("cp.async.wait_group 1;\n" ::);
        } else {
            asm volatile("cp.async.wait_group 0;\n" ::);
        }
        __syncthreads();

        const bool skip = (j * 64 > row0g + 15);
        if (!skip) {
            float* Kb = Ks + (j & 1) * 64 * KST;
            float* Vb = Vs + (j & 1) * 64 * VST;

            // ---- S = (Q*scale) @ K^T : 16 x 64 per warp
            float s[8][4];
            #pragma unroll
            for (int t = 0; t < 8; t++)
                #pragma unroll
                for (int e = 0; e < 4; e++) s[t][e] = 0.0f;

            #pragma unroll
            for (int kk = 0; kk < 8; kk++) {
                #pragma unroll
                for (int t = 0; t < 8; t++) {
                    const uint32_t b0 = __float_as_uint(Kb[(t * 8 + g) * KST + kk * 8 + c]);
                    const uint32_t b1 = __float_as_uint(Kb[(t * 8 + g) * KST + kk * 8 + c + 4]);
                    mma_tf32(s[t], aQ[kk], b0, b1);
                }
            }

            // ---- causal mask (near diagonal only)
            if (j * 64 + 63 > row0g) {
                const int r0 = row0g + g, r1 = r0 + 8;
                #pragma unroll
                for (int t = 0; t < 8; t++) {
                    const int col = j * 64 + t * 8 + 2 * c;
                    if (col     > r0) s[t][0] = -INFINITY;
                    if (col + 1 > r0) s[t][1] = -INFINITY;
                    if (col     > r1) s[t][2] = -INFINITY;
                    if (col + 1 > r1) s[t][3] = -INFINITY;
                }
            }

            // ---- online softmax (2 rows per thread)
            float mx0 = -INFINITY, mx1 = -INFINITY;
            #pragma unroll
            for (int t = 0; t < 8; t++) {
                mx0 = fmaxf(mx0, fmaxf(s[t][0], s[t][1]));
                mx1 = fmaxf(mx1, fmaxf(s[t][2], s[t][3]));
            }
            mx0 = fmaxf(mx0, __shfl_xor_sync(0xffffffffu, mx0, 1));
            mx0 = fmaxf(mx0, __shfl_xor_sync(0xffffffffu, mx0, 2));
            mx1 = fmaxf(mx1, __shfl_xor_sync(0xffffffffu, mx1, 1));
            mx1 = fmaxf(mx1, __shfl_xor_sync(0xffffffffu, mx1, 2));

            const float mn0 = fmaxf(m0v, mx0);
            const float mn1 = fmaxf(m1v, mx1);
            float sum0 = 0.0f, sum1 = 0.0f;
            #pragma unroll
            for (int t = 0; t < 8; t++) {
                s[t][0] = __expf(s[t][0] - mn0);
                s[t][1] = __expf(s[t][1] - mn0);
                s[t][2] = __expf(s[t][2] - mn1);
                s[t][3] = __expf(s[t][3] - mn1);
                sum0 += s[t][0] + s[t][1];
                sum1 += s[t][2] + s[t][3];
            }
            sum0 += __shfl_xor_sync(0xffffffffu, sum0, 1);
            sum0 += __shfl_xor_sync(0xffffffffu, sum0, 2);
            sum1 += __shfl_xor_sync(0xffffffffu, sum1, 1);
            sum1 += __shfl_xor_sync(0xffffffffu, sum1, 2);

            const float al0 = __expf(m0v - mn0);
            const float al1 = __expf(m1v - mn1);
            l0 = l0 * al0 + sum0;
            l1 = l1 * al1 + sum1;
            m0v = mn0; m1v = mn1;

            #pragma unroll
            for (int t = 0; t < 8; t++) {
                o[t][0] *= al0; o[t][1] *= al0;
                o[t][2] *= al1; o[t][3] *= al1;
            }

            // ---- P (rounded to tf32) -> warp-private smem, C->A layout remap
            float* Pw = Ps + (w * 16) * PST;
            __syncwarp();
            #pragma unroll
            for (int t = 0; t < 8; t++) {
                *(float2*)&Pw[ g      * PST + t * 8 + 2 * c] =
                    make_float2(roundtf(s[t][0]), roundtf(s[t][1]));
                *(float2*)&Pw[(g + 8) * PST + t * 8 + 2 * c] =
                    make_float2(roundtf(s[t][2]), roundtf(s[t][3]));
            }
            __syncwarp();

            // ---- O += P @ V
            #pragma unroll
            for (int kk = 0; kk < 8; kk++) {
                uint32_t a[4];
                a[0] = __float_as_uint(Pw[ g      * PST + kk * 8 + c]);
                a[1] = __float_as_uint(Pw[(g + 8) * PST + kk * 8 + c]);
                a[2] = __float_as_uint(Pw[ g      * PST + kk * 8 + c + 4]);
                a[3] = __float_as_uint(Pw[(g + 8) * PST + kk * 8 + c + 4]);
                #pragma unroll
                for (int t = 0; t < 8; t++) {
                    const uint32_t b0 = __float_as_uint(Vb[(kk * 8 + c)     * VST + t * 8 + g]);
                    const uint32_t b1 = __float_as_uint(Vb[(kk * 8 + c + 4) * VST + t * 8 + g]);
                    mma_tf32(o[t], a, b0, b1);
                }
            }
        }
        __syncthreads();
    }

    // ---- write out (tf32-rounded for the O-projection GEMM)
    const int b = bh >> 4, h = bh & 15;
    float* Og = g_ao + ((size_t)(b * NN + qt * 128)) * DD + h * DHH;
    const float i0 = 1.0f / l0, i1 = 1.0f / l1;
    const int r0 = w * 16 + g, r1 = r0 + 8;
    #pragma unroll
    for (int t = 0; t < 8; t++) {
        *(float2*)&Og[(size_t)r0 * DD + t * 8 + 2 * c] =
            make_float2(roundtf(o[t][0] * i0), roundtf(o[t][1] * i0));
        *(float2*)&Og[(size_t)r1 * DD + t * 8 + 2 * c] =
            make_float2(roundtf(o[t][2] * i1), roundtf(o[t][3] * i1));
    }
}

// ============================================================================
// Launch
// ============================================================================
extern "C" void kernel_launch(void* const* d_in, const int* in_sizes, int n_in,
                              void* d_out, int out_size) {
    (void)in_sizes; (void)n_in; (void)out_size;
    const float* x   = (const float*)d_in[0];
    const float* g   = (const float*)d_in[1];
    const float* Wq  = (const float*)d_in[2];
    const float* Wkv = (const float*)d_in[3];
    const float* Wo  = (const float*)d_in[4];
    float* out = (float*)d_out;

    cudaFuncSetAttribute(gemm_tf32<0>, cudaFuncAttributeMaxDynamicSharedMemorySize,
                         GEMM_SMEM_BYTES);
    cudaFuncSetAttribute(gemm_tf32<1>, cudaFuncAttributeMaxDynamicSharedMemorySize,
                         GEMM_SMEM_BYTES);
    cudaFuncSetAttribute(attn_kernel, cudaFuncAttributeMaxDynamicSharedMemorySize,
                         ATTN_SMEM_BYTES);

    // 0) Round weights to tf32
    round_weights<<<4096, 256>>>(Wq, Wkv, Wo);

    // 1) LayerNorm (tf32-rounded output)
    ln_kernel<<<MROWS, 256>>>(x, g);

    // 2) Fused QKV projection (M=8192, N=3072)
    gemm_tf32<0><<<dim3(24, 64), 256, GEMM_SMEM_BYTES>>>(nullptr);

    // 3) Causal flash attention (128-row q tiles)
    attn_kernel<<<dim3(16, BB * HH), 256, ATTN_SMEM_BYTES>>>();

    // 4) Output projection (M=8192, N=1024)
    gemm_tf32<1><<<dim3(8, 64), 256, GEMM_SMEM_BYTES>>>(out);
}

// round 5
// speedup vs baseline: 1.7463x; 1.0089x over previous
#include <cuda_runtime.h>
#include <mma.h>
#include <cstdint>

using namespace nvcuda;

#define BB 4
#define NN 2048
#define DD 1024
#define HH 16
#define DHH 64
#define MROWS (BB * NN)   // 8192

// ---------------- scratch (device globals; no runtime allocation) ----------
__device__ float g_xn[(size_t)MROWS * DD];   // tf32-rounded LN output
__device__ float g_q [(size_t)MROWS * DD];   // [b,h,n,dh], tf32-rounded
__device__ float g_k [(size_t)MROWS * DD];
__device__ float g_v [(size_t)MROWS * DD];
__device__ float g_ao[(size_t)MROWS * DD];   // [b,n,(h dh)], tf32-rounded
__device__ float g_wq [(size_t)DD * DD];     // tf32-rounded weights (row-major)
__device__ float g_wkv[(size_t)DD * 2 * DD];
__device__ float g_wo [(size_t)DD * DD];

// ---------------- PTX helpers ----------------------------------------------
__device__ __forceinline__ uint32_t f2tf32(float f) {
    uint32_t u;
    asm("cvt.rna.tf32.f32 %0, %1;" : "=r"(u) : "f"(f));
    return u;
}
__device__ __forceinline__ float roundtf(float f) { return __uint_as_float(f2tf32(f)); }

__device__ __forceinline__ void mma_tf32(float* d, const uint32_t* a,
                                         uint32_t b0, uint32_t b1) {
    asm volatile(
        "mma.sync.aligned.m16n8k8.row.col.f32.tf32.tf32.f32 "
        "{%0,%1,%2,%3},{%4,%5,%6,%7},{%8,%9},{%0,%1,%2,%3};\n"
        : "+f"(d[0]), "+f"(d[1]), "+f"(d[2]), "+f"(d[3])
        : "r"(a[0]), "r"(a[1]), "r"(a[2]), "r"(a[3]), "r"(b0), "r"(b1));
}
__device__ __forceinline__ void cp16(uint32_t dst, const void* src) {
    asm volatile("cp.async.cg.shared.global [%0], [%1], 16;\n" :: "r"(dst), "l"(src));
}
__device__ __forceinline__ void cp_commit() {
    asm volatile("cp.async.commit_group;\n" ::);
}

// ============================================================================
// Round weights to tf32 once per launch (row-major kept).
// ============================================================================
__global__ void round_weights(const float* __restrict__ wq,
                              const float* __restrict__ wkv,
                              const float* __restrict__ wo) {
    const int i = blockIdx.x * blockDim.x + threadIdx.x;  // float4 index
    const float4* src; float4* dst; int off;
    if (i < 262144)      { src = (const float4*)wq;  dst = (float4*)g_wq;  off = i; }
    else if (i < 786432) { src = (const float4*)wkv; dst = (float4*)g_wkv; off = i - 262144; }
    else                 { src = (const float4*)wo;  dst = (float4*)g_wo;  off = i - 786432; }
    float4 v = src[off];
    v.x = roundtf(v.x); v.y = roundtf(v.y); v.z = roundtf(v.z); v.w = roundtf(v.w);
    dst[off] = v;
}

// ============================================================================
// LayerNorm: one block per row, 256 threads, tf32-rounded output.
// ============================================================================
__global__ void ln_kernel(const float* __restrict__ x, const float* __restrict__ g) {
    const int row = blockIdx.x;
    const int tid = threadIdx.x;
    const float4* xr = (const float4*)(x + (size_t)row * DD);
    float4 v = xr[tid];
    float s  = v.x + v.y + v.z + v.w;
    float ss = v.x*v.x + v.y*v.y + v.z*v.z + v.w*v.w;
    #pragma unroll
    for (int off = 16; off > 0; off >>= 1) {
        s  += __shfl_down_sync(0xffffffffu, s,  off);
        ss += __shfl_down_sync(0xffffffffu, ss, off);
    }
    __shared__ float s1[8], s2[8];
    __shared__ float mu_s, rstd_s;
    const int lane = tid & 31, wid = tid >> 5;
    if (lane == 0) { s1[wid] = s; s2[wid] = ss; }
    __syncthreads();
    if (tid == 0) {
        float t = 0.f, tt = 0.f;
        #pragma unroll
        for (int i = 0; i < 8; i++) { t += s1[i]; tt += s2[i]; }
        float mu  = t * (1.0f / DD);
        float var = tt * (1.0f / DD) - mu * mu;
        mu_s = mu;
        rstd_s = rsqrtf(var + 1e-5f);
    }
    __syncthreads();
    const float mu = mu_s, rstd = rstd_s;
    float4 gv = ((const float4*)g)[tid];
    float4 o;
    o.x = roundtf((v.x - mu) * rstd * gv.x);
    o.y = roundtf((v.y - mu) * rstd * gv.y);
    o.z = roundtf((v.z - mu) * rstd * gv.z);
    o.w = roundtf((v.w - mu) * rstd * gv.w);
    ((float4*)(g_xn + (size_t)row * DD))[tid] = o;
}

// ============================================================================
// TF32 wmma GEMM v2: CTA tile 256x128, 8 warps (4 in M x 2 in N), warp 64x64.
// Double-buffered cp.async, K chunk 32. Operands pre-rounded tf32 (no cvt).
// MODE 0: C = g_xn @ [g_wq | g_wkv] -> scatter tf32-rounded into g_q/g_k/g_v
// MODE 1: C = g_ao @ g_wo           -> dense fp32 output
// ============================================================================
#define ASTR 40
#define BSTR 132
#define GEMM_AS (256 * ASTR)
#define GEMM_BS (32 * BSTR)
#define GEMM_SMEM_BYTES ((2 * GEMM_AS + 2 * GEMM_BS) * 4)

template<int MODE>
__global__ __launch_bounds__(256, 1) void gemm_tf32(float* __restrict__ C) {
    extern __shared__ float sm[];
    float* Asm[2] = { sm, sm + GEMM_AS };
    float* Bsm[2] = { sm + 2 * GEMM_AS, sm + 2 * GEMM_AS + GEMM_BS };
    const uint32_t sbase = (uint32_t)__cvta_generic_to_shared(sm);

    const float* A = (MODE == 0) ? g_xn : g_ao;

    const int m0 = blockIdx.y * 256;
    const int c0 = blockIdx.x * 128;

    const float* Bsrc;
    int ldb, bcol0;
    if (MODE == 1)      { Bsrc = g_wo;  ldb = 1024; bcol0 = c0; }
    else if (c0 < 1024) { Bsrc = g_wq;  ldb = 1024; bcol0 = c0; }
    else                { Bsrc = g_wkv; ldb = 2048; bcol0 = c0 - 1024; }

    const int tid = threadIdx.x;
    const int wid = tid >> 5;
    const int warp_m = wid & 3;   // 4 warps in M, 64 rows each
    const int warp_n = wid >> 2;  // 2 warps in N, 64 cols each

    wmma::fragment<wmma::accumulator, 16, 16, 8, float> acc[4][4];
    #pragma unroll
    for (int i = 0; i < 4; i++)
        #pragma unroll
        for (int j = 0; j < 4; j++)
            wmma::fill_fragment(acc[i][j], 0.0f);

    const int arow = tid >> 3, ac4 = (tid & 7) * 4;   // A: 32 rows/pass x 8 passes
    const int brow = tid >> 5, bc4 = (tid & 31) * 4;  // B: 8 rows/pass x 4 passes

    auto load_tile = [&](int k0, int buf) {
        const uint32_t abase = sbase + (uint32_t)(buf * GEMM_AS) * 4;
        const uint32_t bbase = sbase + (uint32_t)(2 * GEMM_AS + buf * GEMM_BS) * 4;
        #pragma unroll
        for (int rr = 0; rr < 8; rr++) {
            const int r = arow + rr * 32;
            cp16(abase + (uint32_t)(r * ASTR + ac4) * 4,
                 &A[(size_t)(m0 + r) * DD + k0 + ac4]);
        }
        #pragma unroll
        for (int rr = 0; rr < 4; rr++) {
            const int r = brow + rr * 8;
            cp16(bbase + (uint32_t)(r * BSTR + bc4) * 4,
                 &Bsrc[(size_t)(k0 + r) * ldb + bcol0 + bc4]);
        }
        cp_commit();
    };

    load_tile(0, 0);
    int buf = 0;
    for (int k0 = 0; k0 < DD; k0 += 32) {
        if (k0 + 32 < DD) {
            load_tile(k0 + 32, buf ^ 1);
            asm volatile("cp.async.wait_group 1;\n" ::);
        } else {
            asm volatile("cp.async.wait_group 0;\n" ::);
        }
        __syncthreads();

        float* As = Asm[buf];
        float* Bs = Bsm[buf];
        #pragma unroll
        for (int kk = 0; kk < 4; kk++) {
            wmma::fragment<wmma::matrix_a, 16, 16, 8, wmma::precision::tf32, wmma::row_major> af[4];
            #pragma unroll
            for (int i = 0; i < 4; i++)
                wmma::load_matrix_sync(af[i], &As[(warp_m * 64 + i * 16) * ASTR + kk * 8], ASTR);
            wmma::fragment<wmma::matrix_b, 16, 16, 8, wmma::precision::tf32, wmma::row_major> bf[4];
            #pragma unroll
            for (int j = 0; j < 4; j++)
                wmma::load_matrix_sync(bf[j], &Bs[(kk * 8) * BSTR + warp_n * 64 + j * 16], BSTR);
            #pragma unroll
            for (int i = 0; i < 4; i++)
                #pragma unroll
                for (int j = 0; j < 4; j++)
                    wmma::mma_sync(acc[i][j], af[i], bf[j], acc[i][j]);
        }
        __syncthreads();
        buf ^= 1;
    }

    // Epilogue
    #pragma unroll
    for (int i = 0; i < 4; i++) {
        #pragma unroll
        for (int j = 0; j < 4; j++) {
            const int row = m0 + warp_m * 64 + i * 16;
            const int col = c0 + warp_n * 64 + j * 16;
            if (MODE == 1) {
                wmma::store_matrix_sync(&C[(size_t)row * DD + col], acc[i][j], DD,
                                        wmma::mem_row_major);
            } else {
                #pragma unroll
                for (int e = 0; e < acc[i][j].num_elements; e++)
                    acc[i][j].x[e] = roundtf(acc[i][j].x[e]);
                float* dst; int cc;
                if (col < 1024)      { dst = g_q; cc = col; }
                else if (col < 2048) { dst = g_k; cc = col - 1024; }
                else                 { dst = g_v; cc = col - 2048; }
                const int b = row >> 11, n = row & 2047;
                const int h = cc >> 6,  dh = cc & 63;
                float* base = dst + (((size_t)(b * HH + h) * NN + n) * DHH + dh);
                wmma::store_matrix_sync(base, acc[i][j], DHH, wmma::mem_row_major);
            }
        }
    }
}

// ============================================================================
// Causal flash attention (unchanged from R3). PTX mma m16n8k8 tf32.
// ============================================================================
#define KST 68
#define VST 72
#define PST 68
#define ATTN_SMEM_BYTES ((2*64*KST + 2*64*VST + 128*PST) * 4)

__global__ __launch_bounds__(256) void attn_kernel() {
    extern __shared__ float sm[];
    float* Ks = sm;
    float* Vs = sm + 2 * 64 * KST;
    float* Ps = sm + 2 * 64 * KST + 2 * 64 * VST;
    const uint32_t sbase = (uint32_t)__cvta_generic_to_shared(sm);
    const uint32_t ks_u = sbase;
    const uint32_t vs_u = sbase + (uint32_t)(2 * 64 * KST) * 4;

    const int qt = blockIdx.x;
    const int bh = blockIdx.y;
    const int tid = threadIdx.x;
    const int w = tid >> 5;
    const int lane = tid & 31;
    const int g = lane >> 2;
    const int c = lane & 3;

    const size_t hoff = (size_t)bh * NN * DHH;
    const float* Qg  = g_q + hoff + (size_t)qt * 128 * DHH;
    const float* Kg0 = g_k + hoff;
    const float* Vg0 = g_v + hoff;

    uint32_t aQ[8][4];
    {
        const int r0 = w * 16 + g, r1 = r0 + 8;
        #pragma unroll
        for (int kk = 0; kk < 8; kk++) {
            aQ[kk][0] = __float_as_uint(Qg[r0 * DHH + kk * 8 + c]     * 0.125f);
            aQ[kk][1] = __float_as_uint(Qg[r1 * DHH + kk * 8 + c]     * 0.125f);
            aQ[kk][2] = __float_as_uint(Qg[r0 * DHH + kk * 8 + c + 4] * 0.125f);
            aQ[kk][3] = __float_as_uint(Qg[r1 * DHH + kk * 8 + c + 4] * 0.125f);
        }
    }

    float o[8][4];
    #pragma unroll
    for (int t = 0; t < 8; t++)
        #pragma unroll
        for (int e = 0; e < 4; e++) o[t][e] = 0.0f;
    float m0v = -INFINITY, m1v = -INFINITY, l0 = 0.0f, l1 = 0.0f;

    const int jmax = 2 * qt + 1;
    const int lr  = tid >> 4;
    const int lc4 = (tid & 15) * 4;

    auto prefetch = [&](int j, int buf) {
        const float* Kg = Kg0 + (size_t)j * 64 * DHH;
        const float* Vg = Vg0 + (size_t)j * 64 * DHH;
        #pragma unroll
        for (int rr = 0; rr < 4; rr++) {
            const int r = lr + rr * 16;
            cp16(ks_u + (uint32_t)((buf * 64 + r) * KST + lc4) * 4, &Kg[r * DHH + lc4]);
            cp16(vs_u + (uint32_t)((buf * 64 + r) * VST + lc4) * 4, &Vg[r * DHH + lc4]);
        }
        cp_commit();
    };

    prefetch(0, 0);
    const int row0g = qt * 128 + w * 16;

    for (int j = 0; j <= jmax; j++) {
        if (j < jmax) {
            prefetch(j + 1, (j + 1) & 1);
            asm volatile("cp.async.wait_group 1;\n" ::);
        } else {
            asm volatile("cp.async.wait_group 0;\n" ::);
        }
        __syncthreads();

        const bool skip = (j * 64 > row0g + 15);
        if (!skip) {
            float* Kb = Ks + (j & 1) * 64 * KST;
            float* Vb = Vs + (j & 1) * 64 * VST;

            float s[8][4];
            #pragma unroll
            for (int t = 0; t < 8; t++)
                #pragma unroll
                for (int e = 0; e < 4; e++) s[t][e] = 0.0f;

            #pragma unroll
            for (int kk = 0; kk < 8; kk++) {
                #pragma unroll
                for (int t = 0; t < 8; t++) {
                    const uint32_t b0 = __float_as_uint(Kb[(t * 8 + g) * KST + kk * 8 + c]);
                    const uint32_t b1 = __float_as_uint(Kb[(t * 8 + g) * KST + kk * 8 + c + 4]);
                    mma_tf32(s[t], aQ[kk], b0, b1);
                }
            }

            if (j * 64 + 63 > row0g) {
                const int r0 = row0g + g, r1 = r0 + 8;
                #pragma unroll
                for (int t = 0; t < 8; t++) {
                    const int col = j * 64 + t * 8 + 2 * c;
                    if (col     > r0) s[t][0] = -INFINITY;
                    if (col + 1 > r0) s[t][1] = -INFINITY;
                    if (col     > r1) s[t][2] = -INFINITY;
                    if (col + 1 > r1) s[t][3] = -INFINITY;
                }
            }

            float mx0 = -INFINITY, mx1 = -INFINITY;
            #pragma unroll
            for (int t = 0; t < 8; t++) {
                mx0 = fmaxf(mx0, fmaxf(s[t][0], s[t][1]));
                mx1 = fmaxf(mx1, fmaxf(s[t][2], s[t][3]));
            }
            mx0 = fmaxf(mx0, __shfl_xor_sync(0xffffffffu, mx0, 1));
            mx0 = fmaxf(mx0, __shfl_xor_sync(0xffffffffu, mx0, 2));
            mx1 = fmaxf(mx1, __shfl_xor_sync(0xffffffffu, mx1, 1));
            mx1 = fmaxf(mx1, __shfl_xor_sync(0xffffffffu, mx1, 2));

            const float mn0 = fmaxf(m0v, mx0);
            const float mn1 = fmaxf(m1v, mx1);
            float sum0 = 0.0f, sum1 = 0.0f;
            #pragma unroll
            for (int t = 0; t < 8; t++) {
                s[t][0] = __expf(s[t][0] - mn0);
                s[t][1] = __expf(s[t][1] - mn0);
                s[t][2] = __expf(s[t][2] - mn1);
                s[t][3] = __expf(s[t][3] - mn1);
                sum0 += s[t][0] + s[t][1];
                sum1 += s[t][2] + s[t][3];
            }
            sum0 += __shfl_xor_sync(0xffffffffu, sum0, 1);
            sum0 += __shfl_xor_sync(0xffffffffu, sum0, 2);
            sum1 += __shfl_xor_sync(0xffffffffu, sum1, 1);
            sum1 += __shfl_xor_sync(0xffffffffu, sum1, 2);

            const float al0 = __expf(m0v - mn0);
            const float al1 = __expf(m1v - mn1);
            l0 = l0 * al0 + sum0;
            l1 = l1 * al1 + sum1;
            m0v = mn0; m1v = mn1;

            #pragma unroll
            for (int t = 0; t < 8; t++) {
                o[t][0] *= al0; o[t][1] *= al0;
                o[t][2] *= al1; o[t][3] *= al1;
            }

            float* Pw = Ps + (w * 16) * PST;
            __syncwarp();
            #pragma unroll
            for (int t = 0; t < 8; t++) {
                *(float2*)&Pw[ g      * PST + t * 8 + 2 * c] =
                    make_float2(roundtf(s[t][0]), roundtf(s[t][1]));
                *(float2*)&Pw[(g + 8) * PST + t * 8 + 2 * c] =
                    make_float2(roundtf(s[t][2]), roundtf(s[t][3]));
            }
            __syncwarp();

            #pragma unroll
            for (int kk = 0; kk < 8; kk++) {
                uint32_t a[4];
                a[0] = __float_as_uint(Pw[ g      * PST + kk * 8 + c]);
                a[1] = __float_as_uint(Pw[(g + 8) * PST + kk * 8 + c]);
                a[2] = __float_as_uint(Pw[ g      * PST + kk * 8 + c + 4]);
                a[3] = __float_as_uint(Pw[(g + 8) * PST + kk * 8 + c + 4]);
                #pragma unroll
                for (int t = 0; t < 8; t++) {
                    const uint32_t b0 = __float_as_uint(Vb[(kk * 8 + c)     * VST + t * 8 + g]);
                    const uint32_t b1 = __float_as_uint(Vb[(kk * 8 + c + 4) * VST + t * 8 + g]);
                    mma_tf32(o[t], a, b0, b1);
                }
            }
        }
        __syncthreads();
    }

    const int b = bh >> 4, h = bh & 15;
    float* Og = g_ao + ((size_t)(b * NN + qt * 128)) * DD + h * DHH;
    const float i0 = 1.0f / l0, i1 = 1.0f / l1;
    const int r0 = w * 16 + g, r1 = r0 + 8;
    #pragma unroll
    for (int t = 0; t < 8; t++) {
        *(float2*)&Og[(size_t)r0 * DD + t * 8 + 2 * c] =
            make_float2(roundtf(o[t][0] * i0), roundtf(o[t][1] * i0));
        *(float2*)&Og[(size_t)r1 * DD + t * 8 + 2 * c] =
            make_float2(roundtf(o[t][2] * i1), roundtf(o[t][3] * i1));
    }
}

// ============================================================================
// Launch
// ============================================================================
extern "C" void kernel_launch(void* const* d_in, const int* in_sizes, int n_in,
                              void* d_out, int out_size) {
    (void)in_sizes; (void)n_in; (void)out_size;
    const float* x   = (const float*)d_in[0];
    const float* g   = (const float*)d_in[1];
    const float* Wq  = (const float*)d_in[2];
    const float* Wkv = (const float*)d_in[3];
    const float* Wo  = (const float*)d_in[4];
    float* out = (float*)d_out;

    cudaFuncSetAttribute(gemm_tf32<0>, cudaFuncAttributeMaxDynamicSharedMemorySize,
                         GEMM_SMEM_BYTES);
    cudaFuncSetAttribute(gemm_tf32<1>, cudaFuncAttributeMaxDynamicSharedMemorySize,
                         GEMM_SMEM_BYTES);
    cudaFuncSetAttribute(attn_kernel, cudaFuncAttributeMaxDynamicSharedMemorySize,
                         ATTN_SMEM_BYTES);

    // 0) Round weights to tf32
    round_weights<<<4096, 256>>>(Wq, Wkv, Wo);

    // 1) LayerNorm (tf32-rounded output)
    ln_kernel<<<MROWS, 256>>>(x, g);

    // 2) Fused QKV projection (M=8192, N=3072), CTA tile 256x128
    gemm_tf32<0><<<dim3(24, 32), 256, GEMM_SMEM_BYTES>>>(nullptr);

    // 3) Causal flash attention (128-row q tiles)
    attn_kernel<<<dim3(16, BB * HH), 256, ATTN_SMEM_BYTES>>>();

    // 4) Output projection (M=8192, N=1024), CTA tile 256x128
    gemm_tf32<1><<<dim3(8, 32), 256, GEMM_SMEM_BYTES>>>(out);
}

// round 6
// speedup vs baseline: 3.2711x; 1.8731x over previous
#include <cuda_runtime.h>
#include <cstdint>

#define BB 4
#define NN 2048
#define DD 1024
#define HH 16
#define DHH 64
#define MROWS (BB * NN)   // 8192

// ---------------- scratch (device globals; no runtime allocation) ----------
__device__ float g_xn[(size_t)MROWS * DD];   // tf32-rounded LN output
__device__ float g_q [(size_t)MROWS * DD];   // [b,h,n,dh]
__device__ float g_k [(size_t)MROWS * DD];   // [b,h,n,dh]
__device__ float g_v [(size_t)MROWS * DD];   // [b,h,dh,n]  (TRANSPOSED)
__device__ float g_ao[(size_t)MROWS * DD];   // [b,n,(h dh)]
__device__ float g_wt [(size_t)3072 * DD];   // [Wq|Wkv]^T rows n=0..3071, tf32
__device__ float g_wot[(size_t)DD * DD];     // Wo^T, tf32

// ---------------- PTX helpers ----------------------------------------------
__device__ __forceinline__ uint32_t f2tf32(float f) {
    uint32_t u;
    asm("cvt.rna.tf32.f32 %0, %1;" : "=r"(u) : "f"(f));
    return u;
}
__device__ __forceinline__ float roundtf(float f) { return __uint_as_float(f2tf32(f)); }

__device__ __forceinline__ void mma_tf32(float* d, const uint32_t* a,
                                         uint32_t b0, uint32_t b1) {
    asm volatile(
        "mma.sync.aligned.m16n8k8.row.col.f32.tf32.tf32.f32 "
        "{%0,%1,%2,%3},{%4,%5,%6,%7},{%8,%9},{%0,%1,%2,%3};\n"
        : "+f"(d[0]), "+f"(d[1]), "+f"(d[2]), "+f"(d[3])
        : "r"(a[0]), "r"(a[1]), "r"(a[2]), "r"(a[3]), "r"(b0), "r"(b1));
}
__device__ __forceinline__ void ldsm4(uint32_t& r0, uint32_t& r1, uint32_t& r2,
                                      uint32_t& r3, uint32_t addr) {
    asm volatile("ldmatrix.sync.aligned.m8n8.x4.shared.b16 {%0,%1,%2,%3}, [%4];"
                 : "=r"(r0), "=r"(r1), "=r"(r2), "=r"(r3) : "r"(addr));
}
__device__ __forceinline__ void cp16(uint32_t dst, const void* src) {
    asm volatile("cp.async.cg.shared.global [%0], [%1], 16;\n" :: "r"(dst), "l"(src));
}
__device__ __forceinline__ void cp_commit() {
    asm volatile("cp.async.commit_group;\n" ::);
}

// ============================================================================
// Round + transpose weights to tf32: g_wt[n][k], g_wot[n][k].
// ============================================================================
__global__ void transpose_round(const float* __restrict__ wq,
                                const float* __restrict__ wkv,
                                const float* __restrict__ wo) {
    __shared__ float t[32][33];
    const int bid = blockIdx.x;
    const float* S; float* D; int Nn, rowbase, ti;
    if (bid < 1024)      { S = wq;  D = g_wt;  Nn = 1024; rowbase = 0;    ti = bid; }
    else if (bid < 3072) { S = wkv; D = g_wt;  Nn = 2048; rowbase = 1024; ti = bid - 1024; }
    else                 { S = wo;  D = g_wot; Nn = 1024; rowbase = 0;    ti = bid - 3072; }
    const int nt = Nn / 32;
    const int k0 = (ti / nt) * 32, n0 = (ti % nt) * 32;
    const int tx = threadIdx.x, ty = threadIdx.y;
    #pragma unroll
    for (int i = 0; i < 4; i++)
        t[ty + i * 8][tx] = roundtf(S[(size_t)(k0 + ty + i * 8) * Nn + n0 + tx]);
    __syncthreads();
    #pragma unroll
    for (int i = 0; i < 4; i++)
        D[(size_t)(rowbase + n0 + ty + i * 8) * DD + k0 + tx] = t[tx][ty + i * 8];
}

// ============================================================================
// LayerNorm: warp per row, no block barriers. tf32-rounded output.
// ============================================================================
__global__ __launch_bounds__(256) void ln_kernel(const float* __restrict__ x,
                                                 const float* __restrict__ g) {
    const int wid = threadIdx.x >> 5, lane = threadIdx.x & 31;
    const int row = blockIdx.x * 8 + wid;
    const float4* xr = (const float4*)(x + (size_t)row * DD);
    const float4* gr = (const float4*)g;
    float4 v[8];
    float s = 0.f, ss = 0.f;
    #pragma unroll
    for (int j = 0; j < 8; j++) {
        v[j] = xr[lane + j * 32];
        s  += v[j].x + v[j].y + v[j].z + v[j].w;
        ss += v[j].x*v[j].x + v[j].y*v[j].y + v[j].z*v[j].z + v[j].w*v[j].w;
    }
    #pragma unroll
    for (int off = 16; off > 0; off >>= 1) {
        s  += __shfl_xor_sync(0xffffffffu, s,  off);
        ss += __shfl_xor_sync(0xffffffffu, ss, off);
    }
    const float mu = s * (1.0f / DD);
    const float rstd = rsqrtf(ss * (1.0f / DD) - mu * mu + 1e-5f);
    float4* orow = (float4*)(g_xn + (size_t)row * DD);
    #pragma unroll
    for (int j = 0; j < 8; j++) {
        float4 gv = gr[lane + j * 32];
        float4 o;
        o.x = roundtf((v[j].x - mu) * rstd * gv.x);
        o.y = roundtf((v[j].y - mu) * rstd * gv.y);
        o.z = roundtf((v[j].z - mu) * rstd * gv.z);
        o.w = roundtf((v[j].w - mu) * rstd * gv.w);
        orow[lane + j * 32] = o;
    }
}

// ============================================================================
// Raw-mma tf32 GEMM: CTA 128x128, 8 warps (2m x 4n), warp 64x32.
// A [m][k], B = W^T [n][k]; XOR-swizzled 128B smem rows; ldmatrix.x4 frags.
// MODE 0: C = g_xn @ W -> scatter into g_q/g_k (row-major heads) and g_v (transposed)
// MODE 1: C = g_ao @ Wo -> dense output
// ============================================================================
#define GT_BYTES 16384                      // one 128x32 f32 tile
#define GEMM_SMEM_BYTES (4 * GT_BYTES)      // 2 buffers x (A + B)

template<int MODE>
__global__ __launch_bounds__(256, 2) void gemm_mma(float* __restrict__ C) {
    extern __shared__ float sm[];
    const uint32_t sb = (uint32_t)__cvta_generic_to_shared(sm);

    const float* A  = (MODE == 0) ? g_xn : g_ao;
    const float* Bt = (MODE == 0) ? g_wt : g_wot;

    const int m0 = blockIdx.y * 128;
    const int c0 = blockIdx.x * 128;

    const int tid = threadIdx.x;
    const int wid = tid >> 5, lane = tid & 31;
    const int wm = wid & 1;        // 2 warps in M, 64 rows
    const int wn = wid >> 1;       // 4 warps in N, 32 cols
    const int Lm = lane >> 3, Li = lane & 7;

    float acc[4][4][4];
    #pragma unroll
    for (int i = 0; i < 4; i++)
        #pragma unroll
        for (int t = 0; t < 4; t++)
            #pragma unroll
            for (int e = 0; e < 4; e++) acc[i][t][e] = 0.0f;

    // loader mapping: 4 passes, each 256 threads cover 32 rows x 8 kchunks
    const int lrow0 = tid >> 3, lkc = tid & 7;

    auto load_tile = [&](int k0, int buf) {
        const uint32_t ab = sb + (uint32_t)buf * 2 * GT_BYTES;
        const uint32_t bb = ab + GT_BYTES;
        #pragma unroll
        for (int i = 0; i < 4; i++) {
            const int row = lrow0 + i * 32;
            const uint32_t off = (uint32_t)(row * 32 + (((lkc ^ (row & 7)) & 7) << 2)) << 2;
            cp16(ab + off, &A [(size_t)(m0 + row) * DD + k0 + lkc * 4]);
            cp16(bb + off, &Bt[(size_t)(c0 + row) * DD + k0 + lkc * 4]);
        }
        cp_commit();
    };

    // per-lane fragment row bases (bytes within a tile)
    uint32_t a_row[4], b_row[2];
    #pragma unroll
    for (int ig = 0; ig < 4; ig++)
        a_row[ig] = (uint32_t)(wm * 64 + ig * 16 + (Lm & 1) * 8 + Li) * 128;
    #pragma unroll
    for (int tp = 0; tp < 2; tp++)
        b_row[tp] = (uint32_t)(wn * 32 + (tp * 2 + (Lm >> 1)) * 8 + Li) * 128;
    const int a_kchi = Lm >> 1;  // added to kk*2
    const int b_kchi = Lm & 1;

    load_tile(0, 0);
    int buf = 0;
    for (int j = 0; j < 32; j++) {
        if (j < 31) {
            load_tile((j + 1) * 32, buf ^ 1);
            asm volatile("cp.async.wait_group 1;\n" ::);
        } else {
            asm volatile("cp.async.wait_group 0;\n" ::);
        }
        __syncthreads();

        const uint32_t ab = sb + (uint32_t)buf * 2 * GT_BYTES;
        const uint32_t bb = ab + GT_BYTES;
        #pragma unroll
        for (int kk = 0; kk < 4; kk++) {
            uint32_t af[4][4];
            const int kca = kk * 2 + a_kchi;
            #pragma unroll
            for (int ig = 0; ig < 4; ig++)
                ldsm4(af[ig][0], af[ig][1], af[ig][2], af[ig][3],
                      ab + a_row[ig] + (uint32_t)(((kca ^ Li) & 7) << 4));
            uint32_t bf[2][4];
            const int kcb = kk * 2 + b_kchi;
            #pragma unroll
            for (int tp = 0; tp < 2; tp++)
                ldsm4(bf[tp][0], bf[tp][1], bf[tp][2], bf[tp][3],
                      bb + b_row[tp] + (uint32_t)(((kcb ^ Li) & 7) << 4));
            #pragma unroll
            for (int ig = 0; ig < 4; ig++)
                #pragma unroll
                for (int t = 0; t < 4; t++)
                    mma_tf32(acc[ig][t], af[ig],
                             bf[t >> 1][(t & 1) * 2], bf[t >> 1][(t & 1) * 2 + 1]);
        }
        __syncthreads();
        buf ^= 1;
    }

    // Epilogue: thread holds (row g / g+8, cols 2c,2c+1) per (ig,t)
    const int g = lane >> 2, cq = lane & 3;
    #pragma unroll
    for (int ig = 0; ig < 4; ig++) {
        #pragma unroll
        for (int t = 0; t < 4; t++) {
            const int row = m0 + wm * 64 + ig * 16 + g;
            const int col = c0 + wn * 32 + t * 8 + 2 * cq;
            float* d = acc[ig][t];
            if (MODE == 1) {
                *(float2*)&C[(size_t)row * DD + col]       = make_float2(d[0], d[1]);
                *(float2*)&C[(size_t)(row + 8) * DD + col] = make_float2(d[2], d[3]);
            } else {
                const int b = row >> 11, n = row & 2047;
                if (col < 2048) {
                    float* dst = (col < 1024) ? g_q : g_k;
                    const int cc = col & 1023;
                    const int h = cc >> 6, dh = cc & 63;
                    float* base = dst + (((size_t)(b * HH + h) * NN) * DHH + dh);
                    *(float2*)&base[(size_t)n * DHH] =
                        make_float2(roundtf(d[0]), roundtf(d[1]));
                    *(float2*)&base[(size_t)(n + 8) * DHH] =
                        make_float2(roundtf(d[2]), roundtf(d[3]));
                } else {
                    // V transposed: g_v[((b*H+h)*DHH + dh)*NN + n]
                    const int cc = col - 2048;
                    const int h = cc >> 6, dh = cc & 63;
                    float* base = g_v + ((size_t)(b * HH + h) * DHH + dh) * NN;
                    base[n]            = roundtf(d[0]);
                    base[NN + n]       = roundtf(d[1]);
                    base[n + 8]        = roundtf(d[2]);
                    base[NN + n + 8]   = roundtf(d[3]);
                }
            }
        }
    }
}

// ============================================================================
// Causal flash attention with ldmatrix fragments. 128 q rows/CTA, 8 warps.
// K smem [kv][dh] (stride 68), V smem [dh][kv] (stride 68, from transposed g_v),
// P smem [q][kv] (stride 68). All strides are ldmatrix conflict-free (17 mod 8 = 1).
// ============================================================================
#define KST 68
#define VST 68
#define PST 68
#define ATTN_SMEM_BYTES ((2*64*KST + 2*64*VST + 128*PST) * 4)

__global__ __launch_bounds__(256) void attn_kernel() {
    extern __shared__ float sm[];
    const uint32_t sbase = (uint32_t)__cvta_generic_to_shared(sm);
    const uint32_t ks_u = sbase;
    const uint32_t vs_u = sbase + (uint32_t)(2 * 64 * KST) * 4;
    const uint32_t ps_u = vs_u + (uint32_t)(2 * 64 * VST) * 4;
    float* Ps = sm + 2 * 64 * KST + 2 * 64 * VST;

    const int qt = blockIdx.x;
    const int bh = blockIdx.y;
    const int tid = threadIdx.x;
    const int w = tid >> 5;
    const int lane = tid & 31;
    const int g = lane >> 2;
    const int c = lane & 3;
    const int Lm = lane >> 3, Li = lane & 7;

    const size_t hoff = (size_t)bh * NN * DHH;
    const float* Qg  = g_q + hoff + (size_t)qt * 128 * DHH;
    const float* Kg0 = g_k + hoff;
    const float* Vg0 = g_v + hoff;   // [dh][n]

    // Q fragments (pre-rounded tf32; *0.125 exact)
    uint32_t aQ[8][4];
    {
        const int r0 = w * 16 + g, r1 = r0 + 8;
        #pragma unroll
        for (int kk = 0; kk < 8; kk++) {
            aQ[kk][0] = __float_as_uint(Qg[r0 * DHH + kk * 8 + c]     * 0.125f);
            aQ[kk][1] = __float_as_uint(Qg[r1 * DHH + kk * 8 + c]     * 0.125f);
            aQ[kk][2] = __float_as_uint(Qg[r0 * DHH + kk * 8 + c + 4] * 0.125f);
            aQ[kk][3] = __float_as_uint(Qg[r1 * DHH + kk * 8 + c + 4] * 0.125f);
        }
    }

    float o[8][4];
    #pragma unroll
    for (int t = 0; t < 8; t++)
        #pragma unroll
        for (int e = 0; e < 4; e++) o[t][e] = 0.0f;
    float m0v = -INFINITY, m1v = -INFINITY, l0 = 0.0f, l1 = 0.0f;

    const int jmax = 2 * qt + 1;
    const int lr  = tid >> 4;          // 0..15
    const int lc4 = (tid & 15) * 4;    // 0..60

    auto prefetch = [&](int j, int buf) {
        const float* Kg = Kg0 + (size_t)j * 64 * DHH;      // rows kv, cols dh
        const float* Vg = Vg0 + (size_t)j * 64;            // rows dh, cols n (stride NN)
        #pragma unroll
        for (int rr = 0; rr < 4; rr++) {
            const int r = lr + rr * 16;
            cp16(ks_u + (uint32_t)((buf * 64 + r) * KST + lc4) * 4, &Kg[r * DHH + lc4]);
            cp16(vs_u + (uint32_t)((buf * 64 + r) * VST + lc4) * 4, &Vg[(size_t)r * NN + lc4]);
        }
        cp_commit();
    };

    prefetch(0, 0);
    const int row0g = qt * 128 + w * 16;

    // per-lane ldmatrix base offsets (bytes)
    const uint32_t kv_frag = (uint32_t)(((Lm >> 1) * 8 + Li) * KST * 4 + (Lm & 1) * 16);
    const uint32_t p_frag  = (uint32_t)(((Lm & 1) * 8 + Li) * PST * 4 + (Lm >> 1) * 16);
    const uint32_t pw_u = ps_u + (uint32_t)(w * 16) * PST * 4 + p_frag;

    for (int j = 0; j <= jmax; j++) {
        if (j < jmax) {
            prefetch(j + 1, (j + 1) & 1);
            asm volatile("cp.async.wait_group 1;\n" ::);
        } else {
            asm volatile("cp.async.wait_group 0;\n" ::);
        }
        __syncthreads();

        const bool skip = (j * 64 > row0g + 15);
        if (!skip) {
            const uint32_t kb_u = ks_u + (uint32_t)((j & 1) * 64) * KST * 4 + kv_frag;
            const uint32_t vb_u = vs_u + (uint32_t)((j & 1) * 64) * VST * 4 + kv_frag;

            // ---- S = (Q*scale) @ K^T
            float s[8][4];
            #pragma unroll
            for (int t = 0; t < 8; t++)
                #pragma unroll
                for (int e = 0; e < 4; e++) s[t][e] = 0.0f;

            #pragma unroll
            for (int kk = 0; kk < 8; kk++) {
                #pragma unroll
                for (int tp = 0; tp < 4; tp++) {
                    uint32_t r0, r1, r2, r3;
                    ldsm4(r0, r1, r2, r3, kb_u + (uint32_t)(tp * 16) * KST * 4 + kk * 32);
                    mma_tf32(s[2 * tp],     aQ[kk], r0, r1);
                    mma_tf32(s[2 * tp + 1], aQ[kk], r2, r3);
                }
            }

            // ---- causal mask (near diagonal only)
            if (j * 64 + 63 > row0g) {
                const int r0 = row0g + g, r1 = r0 + 8;
                #pragma unroll
                for (int t = 0; t < 8; t++) {
                    const int col = j * 64 + t * 8 + 2 * c;
                    if (col     > r0) s[t][0] = -INFINITY;
                    if (col + 1 > r0) s[t][1] = -INFINITY;
                    if (col     > r1) s[t][2] = -INFINITY;
                    if (col + 1 > r1) s[t][3] = -INFINITY;
                }
            }

            // ---- online softmax (2 rows per thread)
            float mx0 = -INFINITY, mx1 = -INFINITY;
            #pragma unroll
            for (int t = 0; t < 8; t++) {
                mx0 = fmaxf(mx0, fmaxf(s[t][0], s[t][1]));
                mx1 = fmaxf(mx1, fmaxf(s[t][2], s[t][3]));
            }
            mx0 = fmaxf(mx0, __shfl_xor_sync(0xffffffffu, mx0, 1));
            mx0 = fmaxf(mx0, __shfl_xor_sync(0xffffffffu, mx0, 2));
            mx1 = fmaxf(mx1, __shfl_xor_sync(0xffffffffu, mx1, 1));
            mx1 = fmaxf(mx1, __shfl_xor_sync(0xffffffffu, mx1, 2));

            const float mn0 = fmaxf(m0v, mx0);
            const float mn1 = fmaxf(m1v, mx1);
            float sum0 = 0.0f, sum1 = 0.0f;
            #pragma unroll
            for (int t = 0; t < 8; t++) {
                s[t][0] = __expf(s[t][0] - mn0);
                s[t][1] = __expf(s[t][1] - mn0);
                s[t][2] = __expf(s[t][2] - mn1);
                s[t][3] = __expf(s[t][3] - mn1);
                sum0 += s[t][0] + s[t][1];
                sum1 += s[t][2] + s[t][3];
            }
            sum0 += __shfl_xor_sync(0xffffffffu, sum0, 1);
            sum0 += __shfl_xor_sync(0xffffffffu, sum0, 2);
            sum1 += __shfl_xor_sync(0xffffffffu, sum1, 1);
            sum1 += __shfl_xor_sync(0xffffffffu, sum1, 2);

            const float al0 = __expf(m0v - mn0);
            const float al1 = __expf(m1v - mn1);
            l0 = l0 * al0 + sum0;
            l1 = l1 * al1 + sum1;
            m0v = mn0; m1v = mn1;

            #pragma unroll
            for (int t = 0; t < 8; t++) {
                o[t][0] *= al0; o[t][1] *= al0;
                o[t][2] *= al1; o[t][3] *= al1;
            }

            // ---- P (tf32) -> warp-private smem
            float* Pw = Ps + (w * 16) * PST;
            __syncwarp();
            #pragma unroll
            for (int t = 0; t < 8; t++) {
                *(float2*)&Pw[ g      * PST + t * 8 + 2 * c] =
                    make_float2(roundtf(s[t][0]), roundtf(s[t][1]));
                *(float2*)&Pw[(g + 8) * PST + t * 8 + 2 * c] =
                    make_float2(roundtf(s[t][2]), roundtf(s[t][3]));
            }
            __syncwarp();

            // ---- O += P @ V  (V^T in smem: rows dh, cols kv)
            #pragma unroll
            for (int kk = 0; kk < 8; kk++) {
                uint32_t a[4];
                ldsm4(a[0], a[1], a[2], a[3], pw_u + kk * 32);
                #pragma unroll
                for (int tp = 0; tp < 4; tp++) {
                    uint32_t r0, r1, r2, r3;
                    ldsm4(r0, r1, r2, r3, vb_u + (uint32_t)(tp * 16) * VST * 4 + kk * 32);
                    mma_tf32(o[2 * tp],     a, r0, r1);
                    mma_tf32(o[2 * tp + 1], a, r2, r3);
                }
            }
        }
        __syncthreads();
    }

    // ---- write out (tf32-rounded for the O-projection GEMM)
    const int b = bh >> 4, h = bh & 15;
    float* Og = g_ao + ((size_t)(b * NN + qt * 128)) * DD + h * DHH;
    const float i0 = 1.0f / l0, i1 = 1.0f / l1;
    const int r0 = w * 16 + g, r1 = r0 + 8;
    #pragma unroll
    for (int t = 0; t < 8; t++) {
        *(float2*)&Og[(size_t)r0 * DD + t * 8 + 2 * c] =
            make_float2(roundtf(o[t][0] * i0), roundtf(o[t][1] * i0));
        *(float2*)&Og[(size_t)r1 * DD + t * 8 + 2 * c] =
            make_float2(roundtf(o[t][2] * i1), roundtf(o[t][3] * i1));
    }
}

// ============================================================================
// Launch
// ============================================================================
extern "C" void kernel_launch(void* const* d_in, const int* in_sizes, int n_in,
                              void* d_out, int out_size) {
    (void)in_sizes; (void)n_in; (void)out_size;
    const float* x   = (const float*)d_in[0];
    const float* g   = (const float*)d_in[1];
    const float* Wq  = (const float*)d_in[2];
    const float* Wkv = (const float*)d_in[3];
    const float* Wo  = (const float*)d_in[4];
    float* out = (float*)d_out;

    cudaFuncSetAttribute(gemm_mma<0>, cudaFuncAttributeMaxDynamicSharedMemorySize,
                         GEMM_SMEM_BYTES);
    cudaFuncSetAttribute(gemm_mma<1>, cudaFuncAttributeMaxDynamicSharedMemorySize,
                         GEMM_SMEM_BYTES);
    cudaFuncSetAttribute(attn_kernel, cudaFuncAttributeMaxDynamicSharedMemorySize,
                         ATTN_SMEM_BYTES);

    // 0) Round + transpose weights (tf32)
    transpose_round<<<4096, dim3(32, 8)>>>(Wq, Wkv, Wo);

    // 1) LayerNorm (warp per row)
    ln_kernel<<<MROWS / 8, 256>>>(x, g);

    // 2) Fused QKV projection (M=8192, N=3072), CTA 128x128
    gemm_mma<0><<<dim3(24, 64), 256, GEMM_SMEM_BYTES>>>(nullptr);

    // 3) Causal flash attention (128-row q tiles)
    attn_kernel<<<dim3(16, BB * HH), 256, ATTN_SMEM_BYTES>>>();

    // 4) Output projection (M=8192, N=1024), CTA 128x128
    gemm_mma<1><<<dim3(8, 64), 256, GEMM_SMEM_BYTES>>>(out);
}

// round 7
// speedup vs baseline: 3.4138x; 1.0436x over previous
#include <cuda_runtime.h>
#include <cstdint>

#define BB 4
#define NN 2048
#define DD 1024
#define HH 16
#define DHH 64
#define MROWS (BB * NN)   // 8192

// ---------------- scratch (device globals; no runtime allocation) ----------
__device__ float g_xn[(size_t)MROWS * DD];   // tf32-rounded LN output
__device__ float g_q [(size_t)MROWS * DD];   // [b,h,n,dh]
__device__ float g_k [(size_t)MROWS * DD];   // [b,h,n,dh]
__device__ float g_v [(size_t)MROWS * DD];   // [b,h,dh,n]  (TRANSPOSED)
__device__ float g_ao[(size_t)MROWS * DD];   // [b,n,(h dh)]
__device__ float g_wt [(size_t)3072 * DD];   // [Wq|Wkv]^T rows n=0..3071, tf32
__device__ float g_wot[(size_t)DD * DD];     // Wo^T, tf32

// ---------------- PTX helpers ----------------------------------------------
__device__ __forceinline__ uint32_t f2tf32(float f) {
    uint32_t u;
    asm("cvt.rna.tf32.f32 %0, %1;" : "=r"(u) : "f"(f));
    return u;
}
__device__ __forceinline__ float roundtf(float f) { return __uint_as_float(f2tf32(f)); }

__device__ __forceinline__ void mma_tf32(float* d, const uint32_t* a,
                                         uint32_t b0, uint32_t b1) {
    asm volatile(
        "mma.sync.aligned.m16n8k8.row.col.f32.tf32.tf32.f32 "
        "{%0,%1,%2,%3},{%4,%5,%6,%7},{%8,%9},{%0,%1,%2,%3};\n"
        : "+f"(d[0]), "+f"(d[1]), "+f"(d[2]), "+f"(d[3])
        : "r"(a[0]), "r"(a[1]), "r"(a[2]), "r"(a[3]), "r"(b0), "r"(b1));
}
__device__ __forceinline__ void ldsm4(uint32_t& r0, uint32_t& r1, uint32_t& r2,
                                      uint32_t& r3, uint32_t addr) {
    asm volatile("ldmatrix.sync.aligned.m8n8.x4.shared.b16 {%0,%1,%2,%3}, [%4];"
                 : "=r"(r0), "=r"(r1), "=r"(r2), "=r"(r3) : "r"(addr));
}
__device__ __forceinline__ void cp16(uint32_t dst, const void* src) {
    asm volatile("cp.async.cg.shared.global [%0], [%1], 16;\n" :: "r"(dst), "l"(src));
}
__device__ __forceinline__ void cp_commit() {
    asm volatile("cp.async.commit_group;\n" ::);
}

// ============================================================================
// Round + transpose weights to tf32: g_wt[n][k], g_wot[n][k].
// ============================================================================
__global__ void transpose_round(const float* __restrict__ wq,
                                const float* __restrict__ wkv,
                                const float* __restrict__ wo) {
    __shared__ float t[32][33];
    const int bid = blockIdx.x;
    const float* S; float* D; int Nn, rowbase, ti;
    if (bid < 1024)      { S = wq;  D = g_wt;  Nn = 1024; rowbase = 0;    ti = bid; }
    else if (bid < 3072) { S = wkv; D = g_wt;  Nn = 2048; rowbase = 1024; ti = bid - 1024; }
    else                 { S = wo;  D = g_wot; Nn = 1024; rowbase = 0;    ti = bid - 3072; }
    const int nt = Nn / 32;
    const int k0 = (ti / nt) * 32, n0 = (ti % nt) * 32;
    const int tx = threadIdx.x, ty = threadIdx.y;
    #pragma unroll
    for (int i = 0; i < 4; i++)
        t[ty + i * 8][tx] = roundtf(S[(size_t)(k0 + ty + i * 8) * Nn + n0 + tx]);
    __syncthreads();
    #pragma unroll
    for (int i = 0; i < 4; i++)
        D[(size_t)(rowbase + n0 + ty + i * 8) * DD + k0 + tx] = t[tx][ty + i * 8];
}

// ============================================================================
// LayerNorm: warp per row, no block barriers. tf32-rounded output.
// ============================================================================
__global__ __launch_bounds__(256) void ln_kernel(const float* __restrict__ x,
                                                 const float* __restrict__ g) {
    const int wid = threadIdx.x >> 5, lane = threadIdx.x & 31;
    const int row = blockIdx.x * 8 + wid;
    const float4* xr = (const float4*)(x + (size_t)row * DD);
    const float4* gr = (const float4*)g;
    float4 v[8];
    float s = 0.f, ss = 0.f;
    #pragma unroll
    for (int j = 0; j < 8; j++) {
        v[j] = xr[lane + j * 32];
        s  += v[j].x + v[j].y + v[j].z + v[j].w;
        ss += v[j].x*v[j].x + v[j].y*v[j].y + v[j].z*v[j].z + v[j].w*v[j].w;
    }
    #pragma unroll
    for (int off = 16; off > 0; off >>= 1) {
        s  += __shfl_xor_sync(0xffffffffu, s,  off);
        ss += __shfl_xor_sync(0xffffffffu, ss, off);
    }
    const float mu = s * (1.0f / DD);
    const float rstd = rsqrtf(ss * (1.0f / DD) - mu * mu + 1e-5f);
    float4* orow = (float4*)(g_xn + (size_t)row * DD);
    #pragma unroll
    for (int j = 0; j < 8; j++) {
        float4 gv = gr[lane + j * 32];
        float4 o;
        o.x = roundtf((v[j].x - mu) * rstd * gv.x);
        o.y = roundtf((v[j].y - mu) * rstd * gv.y);
        o.z = roundtf((v[j].z - mu) * rstd * gv.z);
        o.w = roundtf((v[j].w - mu) * rstd * gv.w);
        orow[lane + j * 32] = o;
    }
}

// ============================================================================
// Raw-mma tf32 GEMM (unchanged from R6): CTA 128x128, 8 warps, warp 64x32.
// ============================================================================
#define GT_BYTES 16384
#define GEMM_SMEM_BYTES (4 * GT_BYTES)

template<int MODE>
__global__ __launch_bounds__(256, 2) void gemm_mma(float* __restrict__ C) {
    extern __shared__ float sm[];
    const uint32_t sb = (uint32_t)__cvta_generic_to_shared(sm);

    const float* A  = (MODE == 0) ? g_xn : g_ao;
    const float* Bt = (MODE == 0) ? g_wt : g_wot;

    const int m0 = blockIdx.y * 128;
    const int c0 = blockIdx.x * 128;

    const int tid = threadIdx.x;
    const int wid = tid >> 5, lane = tid & 31;
    const int wm = wid & 1;
    const int wn = wid >> 1;
    const int Lm = lane >> 3, Li = lane & 7;

    float acc[4][4][4];
    #pragma unroll
    for (int i = 0; i < 4; i++)
        #pragma unroll
        for (int t = 0; t < 4; t++)
            #pragma unroll
            for (int e = 0; e < 4; e++) acc[i][t][e] = 0.0f;

    const int lrow0 = tid >> 3, lkc = tid & 7;

    auto load_tile = [&](int k0, int buf) {
        const uint32_t ab = sb + (uint32_t)buf * 2 * GT_BYTES;
        const uint32_t bb = ab + GT_BYTES;
        #pragma unroll
        for (int i = 0; i < 4; i++) {
            const int row = lrow0 + i * 32;
            const uint32_t off = (uint32_t)(row * 32 + (((lkc ^ (row & 7)) & 7) << 2)) << 2;
            cp16(ab + off, &A [(size_t)(m0 + row) * DD + k0 + lkc * 4]);
            cp16(bb + off, &Bt[(size_t)(c0 + row) * DD + k0 + lkc * 4]);
        }
        cp_commit();
    };

    uint32_t a_row[4], b_row[2];
    #pragma unroll
    for (int ig = 0; ig < 4; ig++)
        a_row[ig] = (uint32_t)(wm * 64 + ig * 16 + (Lm & 1) * 8 + Li) * 128;
    #pragma unroll
    for (int tp = 0; tp < 2; tp++)
        b_row[tp] = (uint32_t)(wn * 32 + (tp * 2 + (Lm >> 1)) * 8 + Li) * 128;
    const int a_kchi = Lm >> 1;
    const int b_kchi = Lm & 1;

    load_tile(0, 0);
    int buf = 0;
    for (int j = 0; j < 32; j++) {
        if (j < 31) {
            load_tile((j + 1) * 32, buf ^ 1);
            asm volatile("cp.async.wait_group 1;\n" ::);
        } else {
            asm volatile("cp.async.wait_group 0;\n" ::);
        }
        __syncthreads();

        const uint32_t ab = sb + (uint32_t)buf * 2 * GT_BYTES;
        const uint32_t bb = ab + GT_BYTES;
        #pragma unroll
        for (int kk = 0; kk < 4; kk++) {
            uint32_t af[4][4];
            const int kca = kk * 2 + a_kchi;
            #pragma unroll
            for (int ig = 0; ig < 4; ig++)
                ldsm4(af[ig][0], af[ig][1], af[ig][2], af[ig][3],
                      ab + a_row[ig] + (uint32_t)(((kca ^ Li) & 7) << 4));
            uint32_t bf[2][4];
            const int kcb = kk * 2 + b_kchi;
            #pragma unroll
            for (int tp = 0; tp < 2; tp++)
                ldsm4(bf[tp][0], bf[tp][1], bf[tp][2], bf[tp][3],
                      bb + b_row[tp] + (uint32_t)(((kcb ^ Li) & 7) << 4));
            #pragma unroll
            for (int ig = 0; ig < 4; ig++)
                #pragma unroll
                for (int t = 0; t < 4; t++)
                    mma_tf32(acc[ig][t], af[ig],
                             bf[t >> 1][(t & 1) * 2], bf[t >> 1][(t & 1) * 2 + 1]);
        }
        __syncthreads();
        buf ^= 1;
    }

    const int g = lane >> 2, cq = lane & 3;
    #pragma unroll
    for (int ig = 0; ig < 4; ig++) {
        #pragma unroll
        for (int t = 0; t < 4; t++) {
            const int row = m0 + wm * 64 + ig * 16 + g;
            const int col = c0 + wn * 32 + t * 8 + 2 * cq;
            float* d = acc[ig][t];
            if (MODE == 1) {
                *(float2*)&C[(size_t)row * DD + col]       = make_float2(d[0], d[1]);
                *(float2*)&C[(size_t)(row + 8) * DD + col] = make_float2(d[2], d[3]);
            } else {
                const int b = row >> 11, n = row & 2047;
                if (col < 2048) {
                    float* dst = (col < 1024) ? g_q : g_k;
                    const int cc = col & 1023;
                    const int h = cc >> 6, dh = cc & 63;
                    float* base = dst + (((size_t)(b * HH + h) * NN) * DHH + dh);
                    *(float2*)&base[(size_t)n * DHH] =
                        make_float2(roundtf(d[0]), roundtf(d[1]));
                    *(float2*)&base[(size_t)(n + 8) * DHH] =
                        make_float2(roundtf(d[2]), roundtf(d[3]));
                } else {
                    const int cc = col - 2048;
                    const int h = cc >> 6, dh = cc & 63;
                    float* base = g_v + ((size_t)(b * HH + h) * DHH + dh) * NN;
                    base[n]            = roundtf(d[0]);
                    base[NN + n]       = roundtf(d[1]);
                    base[n + 8]        = roundtf(d[2]);
                    base[NN + n + 8]   = roundtf(d[3]);
                }
            }
        }
    }
}

// ============================================================================
// Causal flash attention v3: no P smem (quad-shuffle C->A fragment remap),
// 2 CTAs/SM target. K smem [kv][dh], V smem [dh][kv], stride 68.
// ============================================================================
#define KST 68
#define VST 68
#define ATTN_SMEM_BYTES ((2*64*KST + 2*64*VST) * 4)

__global__ __launch_bounds__(256, 2) void attn_kernel() {
    extern __shared__ float sm[];
    const uint32_t sbase = (uint32_t)__cvta_generic_to_shared(sm);
    const uint32_t ks_u = sbase;
    const uint32_t vs_u = sbase + (uint32_t)(2 * 64 * KST) * 4;

    const int qt = blockIdx.x;
    const int bh = blockIdx.y;
    const int tid = threadIdx.x;
    const int w = tid >> 5;
    const int lane = tid & 31;
    const int g = lane >> 2;
    const int c = lane & 3;
    const int Lm = lane >> 3, Li = lane & 7;

    const size_t hoff = (size_t)bh * NN * DHH;
    const float* Qg  = g_q + hoff + (size_t)qt * 128 * DHH;
    const float* Kg0 = g_k + hoff;
    const float* Vg0 = g_v + hoff;   // [dh][n]

    // Q fragments (pre-rounded tf32; *0.125 exact)
    uint32_t aQ[8][4];
    {
        const int r0 = w * 16 + g, r1 = r0 + 8;
        #pragma unroll
        for (int kk = 0; kk < 8; kk++) {
            aQ[kk][0] = __float_as_uint(Qg[r0 * DHH + kk * 8 + c]     * 0.125f);
            aQ[kk][1] = __float_as_uint(Qg[r1 * DHH + kk * 8 + c]     * 0.125f);
            aQ[kk][2] = __float_as_uint(Qg[r0 * DHH + kk * 8 + c + 4] * 0.125f);
            aQ[kk][3] = __float_as_uint(Qg[r1 * DHH + kk * 8 + c + 4] * 0.125f);
        }
    }

    float o[8][4];
    #pragma unroll
    for (int t = 0; t < 8; t++)
        #pragma unroll
        for (int e = 0; e < 4; e++) o[t][e] = 0.0f;
    float m0v = -INFINITY, m1v = -INFINITY, l0 = 0.0f, l1 = 0.0f;

    const int jmax = 2 * qt + 1;
    const int lr  = tid >> 4;
    const int lc4 = (tid & 15) * 4;

    auto prefetch = [&](int j, int buf) {
        const float* Kg = Kg0 + (size_t)j * 64 * DHH;
        const float* Vg = Vg0 + (size_t)j * 64;
        #pragma unroll
        for (int rr = 0; rr < 4; rr++) {
            const int r = lr + rr * 16;
            cp16(ks_u + (uint32_t)((buf * 64 + r) * KST + lc4) * 4, &Kg[r * DHH + lc4]);
            cp16(vs_u + (uint32_t)((buf * 64 + r) * VST + lc4) * 4, &Vg[(size_t)r * NN + lc4]);
        }
        cp_commit();
    };

    prefetch(0, 0);
    const int row0g = qt * 128 + w * 16;

    const uint32_t kv_frag = (uint32_t)(((Lm >> 1) * 8 + Li) * KST * 4 + (Lm & 1) * 16);
    const int qsrc0 = (lane & ~3) | (c >> 1);   // shuffle source lanes for P remap
    const int qsrc1 = qsrc0 + 2;
    const bool codd = (c & 1);

    for (int j = 0; j <= jmax; j++) {
        if (j < jmax) {
            prefetch(j + 1, (j + 1) & 1);
            asm volatile("cp.async.wait_group 1;\n" ::);
        } else {
            asm volatile("cp.async.wait_group 0;\n" ::);
        }
        __syncthreads();

        const bool skip = (j * 64 > row0g + 15);
        if (!skip) {
            const uint32_t kb_u = ks_u + (uint32_t)((j & 1) * 64) * KST * 4 + kv_frag;
            const uint32_t vb_u = vs_u + (uint32_t)((j & 1) * 64) * VST * 4 + kv_frag;

            // ---- S = (Q*scale) @ K^T
            float s[8][4];
            #pragma unroll
            for (int t = 0; t < 8; t++)
                #pragma unroll
                for (int e = 0; e < 4; e++) s[t][e] = 0.0f;

            #pragma unroll
            for (int kk = 0; kk < 8; kk++) {
                #pragma unroll
                for (int tp = 0; tp < 4; tp++) {
                    uint32_t r0, r1, r2, r3;
                    ldsm4(r0, r1, r2, r3, kb_u + (uint32_t)(tp * 16) * KST * 4 + kk * 32);
                    mma_tf32(s[2 * tp],     aQ[kk], r0, r1);
                    mma_tf32(s[2 * tp + 1], aQ[kk], r2, r3);
                }
            }

            // ---- causal mask (near diagonal only)
            if (j * 64 + 63 > row0g) {
                const int r0 = row0g + g, r1 = r0 + 8;
                #pragma unroll
                for (int t = 0; t < 8; t++) {
                    const int col = j * 64 + t * 8 + 2 * c;
                    if (col     > r0) s[t][0] = -INFINITY;
                    if (col + 1 > r0) s[t][1] = -INFINITY;
                    if (col     > r1) s[t][2] = -INFINITY;
                    if (col + 1 > r1) s[t][3] = -INFINITY;
                }
            }

            // ---- online softmax (2 rows per thread)
            float mx0 = -INFINITY, mx1 = -INFINITY;
            #pragma unroll
            for (int t = 0; t < 8; t++) {
                mx0 = fmaxf(mx0, fmaxf(s[t][0], s[t][1]));
                mx1 = fmaxf(mx1, fmaxf(s[t][2], s[t][3]));
            }
            mx0 = fmaxf(mx0, __shfl_xor_sync(0xffffffffu, mx0, 1));
            mx0 = fmaxf(mx0, __shfl_xor_sync(0xffffffffu, mx0, 2));
            mx1 = fmaxf(mx1, __shfl_xor_sync(0xffffffffu, mx1, 1));
            mx1 = fmaxf(mx1, __shfl_xor_sync(0xffffffffu, mx1, 2));

            const float mn0 = fmaxf(m0v, mx0);
            const float mn1 = fmaxf(m1v, mx1);
            float sum0 = 0.0f, sum1 = 0.0f;
            #pragma unroll
            for (int t = 0; t < 8; t++) {
                s[t][0] = __expf(s[t][0] - mn0);
                s[t][1] = __expf(s[t][1] - mn0);
                s[t][2] = __expf(s[t][2] - mn1);
                s[t][3] = __expf(s[t][3] - mn1);
                sum0 += s[t][0] + s[t][1];
                sum1 += s[t][2] + s[t][3];
            }
            sum0 += __shfl_xor_sync(0xffffffffu, sum0, 1);
            sum0 += __shfl_xor_sync(0xffffffffu, sum0, 2);
            sum1 += __shfl_xor_sync(0xffffffffu, sum1, 1);
            sum1 += __shfl_xor_sync(0xffffffffu, sum1, 2);

            const float al0 = __expf(m0v - mn0);
            const float al1 = __expf(m1v - mn1);
            l0 = l0 * al0 + sum0;
            l1 = l1 * al1 + sum1;
            m0v = mn0; m1v = mn1;

            #pragma unroll
            for (int t = 0; t < 8; t++) {
                o[t][0] *= al0; o[t][1] *= al0;
                o[t][2] *= al1; o[t][3] *= al1;
            }

            // ---- O += P @ V : C-frag -> A-frag via quad shuffles, no smem
            #pragma unroll
            for (int kk = 0; kk < 8; kk++) {
                const float x0 = __shfl_sync(0xffffffffu, s[kk][0], qsrc0);
                const float x1 = __shfl_sync(0xffffffffu, s[kk][1], qsrc0);
                const float x2 = __shfl_sync(0xffffffffu, s[kk][2], qsrc0);
                const float x3 = __shfl_sync(0xffffffffu, s[kk][3], qsrc0);
                const float y0 = __shfl_sync(0xffffffffu, s[kk][0], qsrc1);
                const float y1 = __shfl_sync(0xffffffffu, s[kk][1], qsrc1);
                const float y2 = __shfl_sync(0xffffffffu, s[kk][2], qsrc1);
                const float y3 = __shfl_sync(0xffffffffu, s[kk][3], qsrc1);
                uint32_t a[4];
                a[0] = f2tf32(codd ? x1 : x0);   // P[g][kk*8+c]
                a[1] = f2tf32(codd ? x3 : x2);   // P[g+8][kk*8+c]
                a[2] = f2tf32(codd ? y1 : y0);   // P[g][kk*8+c+4]
                a[3] = f2tf32(codd ? y3 : y2);   // P[g+8][kk*8+c+4]
                #pragma unroll
                for (int tp = 0; tp < 4; tp++) {
                    uint32_t r0, r1, r2, r3;
                    ldsm4(r0, r1, r2, r3, vb_u + (uint32_t)(tp * 16) * VST * 4 + kk * 32);
                    mma_tf32(o[2 * tp],     a, r0, r1);
                    mma_tf32(o[2 * tp + 1], a, r2, r3);
                }
            }
        }
        __syncthreads();
    }

    // ---- write out (tf32-rounded for the O-projection GEMM)
    const int b = bh >> 4, h = bh & 15;
    float* Og = g_ao + ((size_t)(b * NN + qt * 128)) * DD + h * DHH;
    const float i0 = 1.0f / l0, i1 = 1.0f / l1;
    const int r0 = w * 16 + g, r1 = r0 + 8;
    #pragma unroll
    for (int t = 0; t < 8; t++) {
        *(float2*)&Og[(size_t)r0 * DD + t * 8 + 2 * c] =
            make_float2(roundtf(o[t][0] * i0), roundtf(o[t][1] * i0));
        *(float2*)&Og[(size_t)r1 * DD + t * 8 + 2 * c] =
            make_float2(roundtf(o[t][2] * i1), roundtf(o[t][3] * i1));
    }
}

// ============================================================================
// Launch
// ============================================================================
extern "C" void kernel_launch(void* const* d_in, const int* in_sizes, int n_in,
                              void* d_out, int out_size) {
    (void)in_sizes; (void)n_in; (void)out_size;
    const float* x   = (const float*)d_in[0];
    const float* g   = (const float*)d_in[1];
    const float* Wq  = (const float*)d_in[2];
    const float* Wkv = (const float*)d_in[3];
    const float* Wo  = (const float*)d_in[4];
    float* out = (float*)d_out;

    cudaFuncSetAttribute(gemm_mma<0>, cudaFuncAttributeMaxDynamicSharedMemorySize,
                         GEMM_SMEM_BYTES);
    cudaFuncSetAttribute(gemm_mma<1>, cudaFuncAttributeMaxDynamicSharedMemorySize,
                         GEMM_SMEM_BYTES);
    cudaFuncSetAttribute(attn_kernel, cudaFuncAttributeMaxDynamicSharedMemorySize,
                         ATTN_SMEM_BYTES);

    // 0) Round + transpose weights (tf32)
    transpose_round<<<4096, dim3(32, 8)>>>(Wq, Wkv, Wo);

    // 1) LayerNorm (warp per row)
    ln_kernel<<<MROWS / 8, 256>>>(x, g);

    // 2) Fused QKV projection (M=8192, N=3072), CTA 128x128
    gemm_mma<0><<<dim3(24, 64), 256, GEMM_SMEM_BYTES>>>(nullptr);

    // 3) Causal flash attention (128-row q tiles, no P smem)
    attn_kernel<<<dim3(16, BB * HH), 256, ATTN_SMEM_BYTES>>>();

    // 4) Output projection (M=8192, N=1024), CTA 128x128
    gemm_mma<1><<<dim3(8, 64), 256, GEMM_SMEM_BYTES>>>(out);
}

// round 8
// speedup vs baseline: 3.5239x; 1.0323x over previous
#include <cuda_runtime.h>
#include <cstdint>

#define BB 4
#define NN 2048
#define DD 1024
#define HH 16
#define DHH 64
#define MROWS (BB * NN)   // 8192

// ---------------- scratch (device globals; no runtime allocation) ----------
__device__ float g_xn[(size_t)MROWS * DD];   // tf32-rounded LN output
__device__ float g_q [(size_t)MROWS * DD];   // [b,h,n,dh]
__device__ float g_k [(size_t)MROWS * DD];   // [b,h,n,dh]
__device__ float g_v [(size_t)MROWS * DD];   // [b,h,dh,n]  (TRANSPOSED)
__device__ float g_ao[(size_t)MROWS * DD];   // [b,n,(h dh)]
__device__ float g_wt [(size_t)3072 * DD];   // [Wq|Wkv]^T rows n=0..3071, tf32
__device__ float g_wot[(size_t)DD * DD];     // Wo^T, tf32

// ---------------- PTX helpers ----------------------------------------------
__device__ __forceinline__ uint32_t f2tf32(float f) {
    uint32_t u;
    asm("cvt.rna.tf32.f32 %0, %1;" : "=r"(u) : "f"(f));
    return u;
}
__device__ __forceinline__ float roundtf(float f) { return __uint_as_float(f2tf32(f)); }
__device__ __forceinline__ float ex2f(float x) {
    float y;
    asm("ex2.approx.ftz.f32 %0, %1;" : "=f"(y) : "f"(x));
    return y;
}

__device__ __forceinline__ void mma_tf32(float* d, const uint32_t* a,
                                         uint32_t b0, uint32_t b1) {
    asm volatile(
        "mma.sync.aligned.m16n8k8.row.col.f32.tf32.tf32.f32 "
        "{%0,%1,%2,%3},{%4,%5,%6,%7},{%8,%9},{%0,%1,%2,%3};\n"
        : "+f"(d[0]), "+f"(d[1]), "+f"(d[2]), "+f"(d[3])
        : "r"(a[0]), "r"(a[1]), "r"(a[2]), "r"(a[3]), "r"(b0), "r"(b1));
}
__device__ __forceinline__ void ldsm4(uint32_t& r0, uint32_t& r1, uint32_t& r2,
                                      uint32_t& r3, uint32_t addr) {
    asm volatile("ldmatrix.sync.aligned.m8n8.x4.shared.b16 {%0,%1,%2,%3}, [%4];"
                 : "=r"(r0), "=r"(r1), "=r"(r2), "=r"(r3) : "r"(addr));
}
__device__ __forceinline__ void cp16(uint32_t dst, const void* src) {
    asm volatile("cp.async.cg.shared.global [%0], [%1], 16;\n" :: "r"(dst), "l"(src));
}
__device__ __forceinline__ void cp_commit() {
    asm volatile("cp.async.commit_group;\n" ::);
}

// ============================================================================
// Round + transpose weights to tf32: g_wt[n][k], g_wot[n][k].
// ============================================================================
__global__ void transpose_round(const float* __restrict__ wq,
                                const float* __restrict__ wkv,
                                const float* __restrict__ wo) {
    __shared__ float t[32][33];
    const int bid = blockIdx.x;
    const float* S; float* D; int Nn, rowbase, ti;
    if (bid < 1024)      { S = wq;  D = g_wt;  Nn = 1024; rowbase = 0;    ti = bid; }
    else if (bid < 3072) { S = wkv; D = g_wt;  Nn = 2048; rowbase = 1024; ti = bid - 1024; }
    else                 { S = wo;  D = g_wot; Nn = 1024; rowbase = 0;    ti = bid - 3072; }
    const int nt = Nn / 32;
    const int k0 = (ti / nt) * 32, n0 = (ti % nt) * 32;
    const int tx = threadIdx.x, ty = threadIdx.y;
    #pragma unroll
    for (int i = 0; i < 4; i++)
        t[ty + i * 8][tx] = roundtf(S[(size_t)(k0 + ty + i * 8) * Nn + n0 + tx]);
    __syncthreads();
    #pragma unroll
    for (int i = 0; i < 4; i++)
        D[(size_t)(rowbase + n0 + ty + i * 8) * DD + k0 + tx] = t[tx][ty + i * 8];
}

// ============================================================================
// LayerNorm: warp per row, no block barriers. tf32-rounded output.
// ============================================================================
__global__ __launch_bounds__(256) void ln_kernel(const float* __restrict__ x,
                                                 const float* __restrict__ g) {
    const int wid = threadIdx.x >> 5, lane = threadIdx.x & 31;
    const int row = blockIdx.x * 8 + wid;
    const float4* xr = (const float4*)(x + (size_t)row * DD);
    const float4* gr = (const float4*)g;
    float4 v[8];
    float s = 0.f, ss = 0.f;
    #pragma unroll
    for (int j = 0; j < 8; j++) {
        v[j] = xr[lane + j * 32];
        s  += v[j].x + v[j].y + v[j].z + v[j].w;
        ss += v[j].x*v[j].x + v[j].y*v[j].y + v[j].z*v[j].z + v[j].w*v[j].w;
    }
    #pragma unroll
    for (int off = 16; off > 0; off >>= 1) {
        s  += __shfl_xor_sync(0xffffffffu, s,  off);
        ss += __shfl_xor_sync(0xffffffffu, ss, off);
    }
    const float mu = s * (1.0f / DD);
    const float rstd = rsqrtf(ss * (1.0f / DD) - mu * mu + 1e-5f);
    float4* orow = (float4*)(g_xn + (size_t)row * DD);
    #pragma unroll
    for (int j = 0; j < 8; j++) {
        float4 gv = gr[lane + j * 32];
        float4 o;
        o.x = roundtf((v[j].x - mu) * rstd * gv.x);
        o.y = roundtf((v[j].y - mu) * rstd * gv.y);
        o.z = roundtf((v[j].z - mu) * rstd * gv.z);
        o.w = roundtf((v[j].w - mu) * rstd * gv.w);
        orow[lane + j * 32] = o;
    }
}

// ============================================================================
// Raw-mma tf32 GEMM: CTA 128x128, 8 warps (2m x 4n), warp 64x32.
// 3-stage cp.async pipeline, ONE __syncthreads per k-chunk.
// ============================================================================
#define GT_BYTES 16384
#define GSTAGE_BYTES (2 * GT_BYTES)
#define GEMM_SMEM_BYTES (3 * GSTAGE_BYTES)

template<int MODE>
__global__ __launch_bounds__(256, 2) void gemm_mma(float* __restrict__ C) {
    extern __shared__ float sm[];
    const uint32_t sb = (uint32_t)__cvta_generic_to_shared(sm);

    const float* A  = (MODE == 0) ? g_xn : g_ao;
    const float* Bt = (MODE == 0) ? g_wt : g_wot;

    const int m0 = blockIdx.y * 128;
    const int c0 = blockIdx.x * 128;

    const int tid = threadIdx.x;
    const int wid = tid >> 5, lane = tid & 31;
    const int wm = wid & 1;
    const int wn = wid >> 1;
    const int Lm = lane >> 3, Li = lane & 7;

    float acc[4][4][4];
    #pragma unroll
    for (int i = 0; i < 4; i++)
        #pragma unroll
        for (int t = 0; t < 4; t++)
            #pragma unroll
            for (int e = 0; e < 4; e++) acc[i][t][e] = 0.0f;

    const int lrow0 = tid >> 3, lkc = tid & 7;

    auto load_tile = [&](int j, int stage) {
        const int k0 = j * 32;
        const uint32_t ab = sb + (uint32_t)stage * GSTAGE_BYTES;
        const uint32_t bb = ab + GT_BYTES;
        #pragma unroll
        for (int i = 0; i < 4; i++) {
            const int row = lrow0 + i * 32;
            const uint32_t off = (uint32_t)(row * 32 + (((lkc ^ (row & 7)) & 7) << 2)) << 2;
            cp16(ab + off, &A [(size_t)(m0 + row) * DD + k0 + lkc * 4]);
            cp16(bb + off, &Bt[(size_t)(c0 + row) * DD + k0 + lkc * 4]);
        }
        cp_commit();
    };

    uint32_t a_row[4], b_row[2];
    #pragma unroll
    for (int ig = 0; ig < 4; ig++)
        a_row[ig] = (uint32_t)(wm * 64 + ig * 16 + (Lm & 1) * 8 + Li) * 128;
    #pragma unroll
    for (int tp = 0; tp < 2; tp++)
        b_row[tp] = (uint32_t)(wn * 32 + (tp * 2 + (Lm >> 1)) * 8 + Li) * 128;
    const int a_kchi = Lm >> 1;
    const int b_kchi = Lm & 1;

    load_tile(0, 0);
    load_tile(1, 1);

    int cb = 0, nb = 2;
    for (int j = 0; j < 32; j++) {
        if (j < 31) asm volatile("cp.async.wait_group 1;\n" ::);
        else        asm volatile("cp.async.wait_group 0;\n" ::);
        __syncthreads();
        if (j + 2 < 32) {
            load_tile(j + 2, nb);
            nb = (nb == 2) ? 0 : nb + 1;
        }

        const uint32_t ab = sb + (uint32_t)cb * GSTAGE_BYTES;
        const uint32_t bb = ab + GT_BYTES;
        #pragma unroll
        for (int kk = 0; kk < 4; kk++) {
            uint32_t af[4][4];
            const int kca = kk * 2 + a_kchi;
            #pragma unroll
            for (int ig = 0; ig < 4; ig++)
                ldsm4(af[ig][0], af[ig][1], af[ig][2], af[ig][3],
                      ab + a_row[ig] + (uint32_t)(((kca ^ Li) & 7) << 4));
            uint32_t bf[2][4];
            const int kcb = kk * 2 + b_kchi;
            #pragma unroll
            for (int tp = 0; tp < 2; tp++)
                ldsm4(bf[tp][0], bf[tp][1], bf[tp][2], bf[tp][3],
                      bb + b_row[tp] + (uint32_t)(((kcb ^ Li) & 7) << 4));
            #pragma unroll
            for (int ig = 0; ig < 4; ig++)
                #pragma unroll
                for (int t = 0; t < 4; t++)
                    mma_tf32(acc[ig][t], af[ig],
                             bf[t >> 1][(t & 1) * 2], bf[t >> 1][(t & 1) * 2 + 1]);
        }
        cb = (cb == 2) ? 0 : cb + 1;
    }

    const int g = lane >> 2, cq = lane & 3;
    #pragma unroll
    for (int ig = 0; ig < 4; ig++) {
        #pragma unroll
        for (int t = 0; t < 4; t++) {
            const int row = m0 + wm * 64 + ig * 16 + g;
            const int col = c0 + wn * 32 + t * 8 + 2 * cq;
            float* d = acc[ig][t];
            if (MODE == 1) {
                *(float2*)&C[(size_t)row * DD + col]       = make_float2(d[0], d[1]);
                *(float2*)&C[(size_t)(row + 8) * DD + col] = make_float2(d[2], d[3]);
            } else {
                const int b = row >> 11, n = row & 2047;
                if (col < 2048) {
                    float* dst = (col < 1024) ? g_q : g_k;
                    const int cc = col & 1023;
                    const int h = cc >> 6, dh = cc & 63;
                    float* base = dst + (((size_t)(b * HH + h) * NN) * DHH + dh);
                    *(float2*)&base[(size_t)n * DHH] =
                        make_float2(roundtf(d[0]), roundtf(d[1]));
                    *(float2*)&base[(size_t)(n + 8) * DHH] =
                        make_float2(roundtf(d[2]), roundtf(d[3]));
                } else {
                    const int cc = col - 2048;
                    const int h = cc >> 6, dh = cc & 63;
                    float* base = g_v + ((size_t)(b * HH + h) * DHH + dh) * NN;
                    base[n]            = roundtf(d[0]);
                    base[NN + n]       = roundtf(d[1]);
                    base[n + 8]        = roundtf(d[2]);
                    base[NN + n + 8]   = roundtf(d[3]);
                }
            }
        }
    }
}

// ============================================================================
// Causal flash attention v4: quad-shuffle P remap, base-2 softmax (scale
// pre-folded into Q), 3-stage K/V pipeline, ONE __syncthreads per tile.
// ============================================================================
#define KST 68
#define VST 68
#define KSTG (64 * KST)
#define VSTG (64 * VST)
#define ATTN_SMEM_BYTES ((3 * KSTG + 3 * VSTG) * 4)

__global__ __launch_bounds__(256, 2) void attn_kernel() {
    extern __shared__ float sm[];
    const uint32_t sbase = (uint32_t)__cvta_generic_to_shared(sm);
    const uint32_t ks_u = sbase;
    const uint32_t vs_u = sbase + (uint32_t)(3 * KSTG) * 4;

    const int qt = (int)gridDim.x - 1 - (int)blockIdx.x;   // heavy tiles first
    const int bh = blockIdx.y;
    const int tid = threadIdx.x;
    const int w = tid >> 5;
    const int lane = tid & 31;
    const int g = lane >> 2;
    const int c = lane & 3;
    const int Lm = lane >> 3, Li = lane & 7;

    const size_t hoff = (size_t)bh * NN * DHH;
    const float* Qg  = g_q + hoff + (size_t)qt * 128 * DHH;
    const float* Kg0 = g_k + hoff;
    const float* Vg0 = g_v + hoff;   // [dh][n]

    // Q fragments, scale 0.125*log2(e) folded in (base-2 softmax domain)
    const float QSCALE = 0.125f * 1.4426950408889634f;
    uint32_t aQ[8][4];
    {
        const int r0 = w * 16 + g, r1 = r0 + 8;
        #pragma unroll
        for (int kk = 0; kk < 8; kk++) {
            aQ[kk][0] = f2tf32(Qg[r0 * DHH + kk * 8 + c]     * QSCALE);
            aQ[kk][1] = f2tf32(Qg[r1 * DHH + kk * 8 + c]     * QSCALE);
            aQ[kk][2] = f2tf32(Qg[r0 * DHH + kk * 8 + c + 4] * QSCALE);
            aQ[kk][3] = f2tf32(Qg[r1 * DHH + kk * 8 + c + 4] * QSCALE);
        }
    }

    float o[8][4];
    #pragma unroll
    for (int t = 0; t < 8; t++)
        #pragma unroll
        for (int e = 0; e < 4; e++) o[t][e] = 0.0f;
    float m0v = -INFINITY, m1v = -INFINITY, l0 = 0.0f, l1 = 0.0f;

    const int jmax = 2 * qt + 1;
    const int lr  = tid >> 4;
    const int lc4 = (tid & 15) * 4;

    auto prefetch = [&](int j, int stage) {
        const float* Kg = Kg0 + (size_t)j * 64 * DHH;
        const float* Vg = Vg0 + (size_t)j * 64;
        #pragma unroll
        for (int rr = 0; rr < 4; rr++) {
            const int r = lr + rr * 16;
            cp16(ks_u + (uint32_t)((stage * 64 + r) * KST + lc4) * 4, &Kg[r * DHH + lc4]);
            cp16(vs_u + (uint32_t)((stage * 64 + r) * VST + lc4) * 4, &Vg[(size_t)r * NN + lc4]);
        }
        cp_commit();
    };

    prefetch(0, 0);
    prefetch(1, 1);   // jmax >= 1 always
    const int row0g = qt * 128 + w * 16;

    const uint32_t kv_frag = (uint32_t)(((Lm >> 1) * 8 + Li) * KST * 4 + (Lm & 1) * 16);
    const int qsrc0 = (lane & ~3) | (c >> 1);
    const int qsrc1 = qsrc0 + 2;
    const bool codd = (c & 1);

    int cbuf = 0, nbuf = 2;
    for (int j = 0; j <= jmax; j++) {
        if (j < jmax) asm volatile("cp.async.wait_group 1;\n" ::);
        else          asm volatile("cp.async.wait_group 0;\n" ::);
        __syncthreads();
        if (j + 2 <= jmax) {
            prefetch(j + 2, nbuf);
            nbuf = (nbuf == 2) ? 0 : nbuf + 1;
        }

        const bool skip = (j * 64 > row0g + 15);
        if (!skip) {
            const uint32_t kb_u = ks_u + (uint32_t)(cbuf * KSTG) * 4 + kv_frag;
            const uint32_t vb_u = vs_u + (uint32_t)(cbuf * VSTG) * 4 + kv_frag;

            // ---- S = (Q*scale*lg2e) @ K^T (base-2 logits)
            float s[8][4];
            #pragma unroll
            for (int t = 0; t < 8; t++)
                #pragma unroll
                for (int e = 0; e < 4; e++) s[t][e] = 0.0f;

            #pragma unroll
            for (int kk = 0; kk < 8; kk++) {
                #pragma unroll
                for (int tp = 0; tp < 4; tp++) {
                    uint32_t r0, r1, r2, r3;
                    ldsm4(r0, r1, r2, r3, kb_u + (uint32_t)(tp * 16) * KST * 4 + kk * 32);
                    mma_tf32(s[2 * tp],     aQ[kk], r0, r1);
                    mma_tf32(s[2 * tp + 1], aQ[kk], r2, r3);
                }
            }

            // ---- causal mask (near diagonal only)
            if (j * 64 + 63 > row0g) {
                const int r0 = row0g + g, r1 = r0 + 8;
                #pragma unroll
                for (int t = 0; t < 8; t++) {
                    const int col = j * 64 + t * 8 + 2 * c;
                    if (col     > r0) s[t][0] = -INFINITY;
                    if (col + 1 > r0) s[t][1] = -INFINITY;
                    if (col     > r1) s[t][2] = -INFINITY;
                    if (col + 1 > r1) s[t][3] = -INFINITY;
                }
            }

            // ---- online softmax, base-2 (2 rows per thread)
            float mx0 = -INFINITY, mx1 = -INFINITY;
            #pragma unroll
            for (int t = 0; t < 8; t++) {
                mx0 = fmaxf(mx0, fmaxf(s[t][0], s[t][1]));
                mx1 = fmaxf(mx1, fmaxf(s[t][2], s[t][3]));
            }
            mx0 = fmaxf(mx0, __shfl_xor_sync(0xffffffffu, mx0, 1));
            mx0 = fmaxf(mx0, __shfl_xor_sync(0xffffffffu, mx0, 2));
            mx1 = fmaxf(mx1, __shfl_xor_sync(0xffffffffu, mx1, 1));
            mx1 = fmaxf(mx1, __shfl_xor_sync(0xffffffffu, mx1, 2));

            const float mn0 = fmaxf(m0v, mx0);
            const float mn1 = fmaxf(m1v, mx1);
            float sum0 = 0.0f, sum1 = 0.0f;
            #pragma unroll
            for (int t = 0; t < 8; t++) {
                s[t][0] = ex2f(s[t][0] - mn0);
                s[t][1] = ex2f(s[t][1] - mn0);
                s[t][2] = ex2f(s[t][2] - mn1);
                s[t][3] = ex2f(s[t][3] - mn1);
                sum0 += s[t][0] + s[t][1];
                sum1 += s[t][2] + s[t][3];
            }
            sum0 += __shfl_xor_sync(0xffffffffu, sum0, 1);
            sum0 += __shfl_xor_sync(0xffffffffu, sum0, 2);
            sum1 += __shfl_xor_sync(0xffffffffu, sum1, 1);
            sum1 += __shfl_xor_sync(0xffffffffu, sum1, 2);

            const float al0 = ex2f(m0v - mn0);
            const float al1 = ex2f(m1v - mn1);
            l0 = l0 * al0 + sum0;
            l1 = l1 * al1 + sum1;
            m0v = mn0; m1v = mn1;

            #pragma unroll
            for (int t = 0; t < 8; t++) {
                o[t][0] *= al0; o[t][1] *= al0;
                o[t][2] *= al1; o[t][3] *= al1;
            }

            // ---- O += P @ V : C-frag -> A-frag via quad shuffles, no smem
            #pragma unroll
            for (int kk = 0; kk < 8; kk++) {
                const float x0 = __shfl_sync(0xffffffffu, s[kk][0], qsrc0);
                const float x1 = __shfl_sync(0xffffffffu, s[kk][1], qsrc0);
                const float x2 = __shfl_sync(0xffffffffu, s[kk][2], qsrc0);
                const float x3 = __shfl_sync(0xffffffffu, s[kk][3], qsrc0);
                const float y0 = __shfl_sync(0xffffffffu, s[kk][0], qsrc1);
                const float y1 = __shfl_sync(0xffffffffu, s[kk][1], qsrc1);
                const float y2 = __shfl_sync(0xffffffffu, s[kk][2], qsrc1);
                const float y3 = __shfl_sync(0xffffffffu, s[kk][3], qsrc1);
                uint32_t a[4];
                a[0] = f2tf32(codd ? x1 : x0);
                a[1] = f2tf32(codd ? x3 : x2);
                a[2] = f2tf32(codd ? y1 : y0);
                a[3] = f2tf32(codd ? y3 : y2);
                #pragma unroll
                for (int tp = 0; tp < 4; tp++) {
                    uint32_t r0, r1, r2, r3;
                    ldsm4(r0, r1, r2, r3, vb_u + (uint32_t)(tp * 16) * VST * 4 + kk * 32);
                    mma_tf32(o[2 * tp],     a, r0, r1);
                    mma_tf32(o[2 * tp + 1], a, r2, r3);
                }
            }
        }
        cbuf = (cbuf == 2) ? 0 : cbuf + 1;
    }

    // ---- write out (tf32-rounded for the O-projection GEMM)
    const int b = bh >> 4, h = bh & 15;
    float* Og = g_ao + ((size_t)(b * NN + qt * 128)) * DD + h * DHH;
    const float i0 = 1.0f / l0, i1 = 1.0f / l1;
    const int r0 = w * 16 + g, r1 = r0 + 8;
    #pragma unroll
    for (int t = 0; t < 8; t++) {
        *(float2*)&Og[(size_t)r0 * DD + t * 8 + 2 * c] =
            make_float2(roundtf(o[t][0] * i0), roundtf(o[t][1] * i0));
        *(float2*)&Og[(size_t)r1 * DD + t * 8 + 2 * c] =
            make_float2(roundtf(o[t][2] * i1), roundtf(o[t][3] * i1));
    }
}

// ============================================================================
// Launch
// ============================================================================
extern "C" void kernel_launch(void* const* d_in, const int* in_sizes, int n_in,
                              void* d_out, int out_size) {
    (void)in_sizes; (void)n_in; (void)out_size;
    const float* x   = (const float*)d_in[0];
    const float* g   = (const float*)d_in[1];
    const float* Wq  = (const float*)d_in[2];
    const float* Wkv = (const float*)d_in[3];
    const float* Wo  = (const float*)d_in[4];
    float* out = (float*)d_out;

    cudaFuncSetAttribute(gemm_mma<0>, cudaFuncAttributeMaxDynamicSharedMemorySize,
                         GEMM_SMEM_BYTES);
    cudaFuncSetAttribute(gemm_mma<1>, cudaFuncAttributeMaxDynamicSharedMemorySize,
                         GEMM_SMEM_BYTES);
    cudaFuncSetAttribute(attn_kernel, cudaFuncAttributeMaxDynamicSharedMemorySize,
                         ATTN_SMEM_BYTES);

    // 0) Round + transpose weights (tf32)
    transpose_round<<<4096, dim3(32, 8)>>>(Wq, Wkv, Wo);

    // 1) LayerNorm (warp per row)
    ln_kernel<<<MROWS / 8, 256>>>(x, g);

    // 2) Fused QKV projection (M=8192, N=3072), CTA 128x128, 3-stage
    gemm_mma<0><<<dim3(24, 64), 256, GEMM_SMEM_BYTES>>>(nullptr);

    // 3) Causal flash attention (128-row q tiles, 3-stage, 1 barrier/tile)
    attn_kernel<<<dim3(16, BB * HH), 256, ATTN_SMEM_BYTES>>>();

    // 4) Output projection (M=8192, N=1024), CTA 128x128, 3-stage
    gemm_mma<1><<<dim3(8, 64), 256, GEMM_SMEM_BYTES>>>(out);
}